// round 9
// baseline (speedup 1.0000x reference)
#include <cuda_runtime.h>
#include <math.h>

#define BT   64
#define NCTA 128
#define NTHR 512
#define TH   20
#define LP   30
#define DTC  0.1f
#define D2C  0.005f

typedef unsigned long long ull;

struct SM {
    ulonglong2 Wp[3][64][32];   // 96KB: [l][k(0..31 x | 32..63 h)][d]: .x={Wi,Wf} .y={Wg,Wo}
    float  Hb[2][3][32][BT];    // 48KB ping-pong h
    float  xb[2][32][BT];       // 16KB ping-pong x / c
    float  XP[24][BT];          // 6KB  [Xx(3), Xy(3), Px(9), Py(9)]
    float  Zs[2][TH][BT];       // 10KB
    float  pred[4][BT];         // 1KB
    float4 bsum2[3][32];        // {bi,bf,bg,bo} per (l,d)
    float  WinT[24][32];        // Win transposed [k][d]
    float  Winb[32];
    float  WoutT[32][4];
    float  Woutb[4];
};

__device__ __forceinline__ float tanha(float x) {
    float y; asm("tanh.approx.f32 %0, %1;" : "=f"(y) : "f"(x)); return y;
}
__device__ __forceinline__ float sigm(float z) {
    return fmaf(tanha(0.5f * z), 0.5f, 0.5f);
}
__device__ __forceinline__ void ffma2(ull& a, ull w, ull x) {
    asm("fma.rn.f32x2 %0, %1, %2, %0;" : "+l"(a) : "l"(w), "l"(x));
}
__device__ __forceinline__ float2 u2f2(ull v) {
    float2 r; asm("mov.b64 {%0, %1}, %2;" : "=f"(r.x), "=f"(r.y) : "l"(v)); return r;
}
__device__ __forceinline__ ull f2u2(float lo, float hi) {
    ull r; asm("mov.b64 %0, {%1, %2};" : "=l"(r) : "f"(lo), "f"(hi)); return r;
}
__device__ __forceinline__ ull dup(float v) {
    ull r; asm("mov.b64 %0, {%1, %1};" : "=l"(r) : "f"(v)); return r;
}

__device__ __forceinline__ void pack_weights(SM& s, int tid,
        const float* __restrict__ Wih, const float* __restrict__ Whh,
        const float* __restrict__ bih, const float* __restrict__ bhh) {
    for (int i = tid; i < 3 * 64 * 32; i += NTHR) {
        int d = i & 31, kk = (i >> 5) & 63, l = i >> 11;
        const float* W = (kk < 32) ? Wih : Whh;
        int k = kk & 31;
        int base = l * 4096 + d * 32 + k;
        float4 v;
        v.x = W[base];
        v.y = W[base + 1024];
        v.z = W[base + 2048];
        v.w = W[base + 3072];
        *reinterpret_cast<float4*>(&s.Wp[l][kk][d]) = v;
    }
    for (int i = tid; i < 96; i += NTHR) {
        int l = i >> 5, d = i & 31;
        int b = l * 128 + d;
        float4 v;
        v.x = bih[b]      + bhh[b];
        v.y = bih[b + 32] + bhh[b + 32];
        v.z = bih[b + 64] + bhh[b + 64];
        v.w = bih[b + 96] + bhh[b + 96];
        s.bsum2[l][d] = v;
    }
}

// Kalman predict with Q[i][j] = g_i * g_j
__device__ __forceinline__ void kpred_f(float X[3], float P[9],
                                        float g0, float g1, float g2) {
    X[0] = X[0] + DTC * X[1] + D2C * X[2];
    X[1] = X[1] + DTC * X[2];
    float A[9];
#pragma unroll
    for (int j = 0; j < 3; j++) {
        A[0 * 3 + j] = P[0 * 3 + j] + DTC * P[1 * 3 + j] + D2C * P[2 * 3 + j];
        A[1 * 3 + j] = P[1 * 3 + j] + DTC * P[2 * 3 + j];
        A[2 * 3 + j] = P[2 * 3 + j];
    }
#pragma unroll
    for (int i = 0; i < 3; i++) {
        float qi = (i == 0) ? g0 : ((i == 1) ? g1 : g2);
        P[i * 3 + 0] = A[i * 3 + 0] + DTC * A[i * 3 + 1] + D2C * A[i * 3 + 2] + qi * g0;
        P[i * 3 + 1] = A[i * 3 + 1] + DTC * A[i * 3 + 2] + qi * g1;
        P[i * 3 + 2] = A[i * 3 + 2] + qi * g2;
    }
}

__device__ __forceinline__ void kupd_f(float X[3], float P[9], float z, float R) {
    float y = z - X[0];
    float S = P[0] + R;
    float inv = 1.0f / S;
    float K0 = P[0] * inv, K1 = P[3] * inv, K2 = P[6] * inv;
    X[0] += y * K0; X[1] += y * K1; X[2] += y * K2;
    float r0 = P[0], r1 = P[1], r2 = P[2];
    P[0] -= K0 * r0; P[1] -= K0 * r1; P[2] -= K0 * r2;
    P[3] -= K1 * r0; P[4] -= K1 * r1; P[5] -= K1 * r2;
    P[6] -= K2 * r0; P[7] -= K2 * r1; P[8] -= K2 * r2;
}

// input layer + 3 LSTM layers. Reads XP; leaves c[2] in s.xb[1].
// Each thread: one dg (0..31), 4 batch. 5 __syncthreads total.
__device__ __forceinline__ void run_stack(SM& s, int bq, int dg, float Creg[3][4], int p) {
    // ---- input layer: x = tanh(XP @ Win^T + b) -> xb[0] ----
    {
        float acc[4];
        float bb = s.Winb[dg];
#pragma unroll
        for (int b = 0; b < 4; b++) acc[b] = bb;
#pragma unroll 6
        for (int k = 0; k < 24; k++) {
            float4 xv = *(const float4*)&s.XP[k][bq * 4];
            float w = s.WinT[k][dg];
            acc[0] = fmaf(w, xv.x, acc[0]);
            acc[1] = fmaf(w, xv.y, acc[1]);
            acc[2] = fmaf(w, xv.z, acc[2]);
            acc[3] = fmaf(w, xv.w, acc[3]);
        }
        float4 r;
        r.x = tanha(acc[0]); r.y = tanha(acc[1]); r.z = tanha(acc[2]); r.w = tanha(acc[3]);
        *(float4*)&s.xb[0][dg][bq * 4] = r;
    }
    __syncthreads();

    // ---- 3 LSTM layers; xb ping-pong: L0: 0->1, L1: 1->0, L2: 0->1 ----
    int q = p ^ 1;
#pragma unroll 1
    for (int l = 0; l < 3; l++) {
        int ra = (l & 1);          // 0,1,0
        int wa = ra ^ 1;           // 1,0,1
        float4 bb = s.bsum2[l][dg];
        ull aif[4], ago[4];
        {
            ull bi = f2u2(bb.x, bb.y), bg = f2u2(bb.z, bb.w);
#pragma unroll
            for (int b = 0; b < 4; b++) { aif[b] = bi; ago[b] = bg; }
        }
        const ulonglong2* __restrict__ wl = &s.Wp[l][0][0];
        const float* __restrict__ xl = &s.xb[ra][0][0];
        const float* __restrict__ hl = &s.Hb[p][l][0][0];
        // x part
#pragma unroll 4
        for (int k = 0; k < 32; k++) {
            float4 xv = *(const float4*)&xl[k * BT + bq * 4];
            ulonglong2 w = wl[k * 32 + dg];
            ull x0 = dup(xv.x), x1 = dup(xv.y), x2 = dup(xv.z), x3 = dup(xv.w);
            ffma2(aif[0], w.x, x0); ffma2(ago[0], w.y, x0);
            ffma2(aif[1], w.x, x1); ffma2(ago[1], w.y, x1);
            ffma2(aif[2], w.x, x2); ffma2(ago[2], w.y, x2);
            ffma2(aif[3], w.x, x3); ffma2(ago[3], w.y, x3);
        }
        // h part
#pragma unroll 4
        for (int k = 0; k < 32; k++) {
            float4 hv = *(const float4*)&hl[k * BT + bq * 4];
            ulonglong2 w = wl[(32 + k) * 32 + dg];
            ull x0 = dup(hv.x), x1 = dup(hv.y), x2 = dup(hv.z), x3 = dup(hv.w);
            ffma2(aif[0], w.x, x0); ffma2(ago[0], w.y, x0);
            ffma2(aif[1], w.x, x1); ffma2(ago[1], w.y, x1);
            ffma2(aif[2], w.x, x2); ffma2(ago[2], w.y, x2);
            ffma2(aif[3], w.x, x3); ffma2(ago[3], w.y, x3);
        }
        // epilogue: writes go to the OTHER buffers -> no barrier needed first
        float cn[4], hn[4];
#pragma unroll
        for (int b = 0; b < 4; b++) {
            float2 vif = u2f2(aif[b]);
            float2 vgo = u2f2(ago[b]);
            float c = fmaf(sigm(vif.y), Creg[l][b], sigm(vif.x) * tanha(vgo.x));
            float h = sigm(vgo.y) * tanha(c);
            Creg[l][b] = c;
            cn[b] = c; hn[b] = h;
        }
        float4 cv, hv;
        cv.x = cn[0]; cv.y = cn[1]; cv.z = cn[2]; cv.w = cn[3];
        hv.x = hn[0]; hv.y = hn[1]; hv.z = hn[2]; hv.w = hn[3];
        *(float4*)&s.xb[wa][dg][bq * 4]    = cv;
        *(float4*)&s.Hb[q][l][dg][bq * 4]  = hv;
        __syncthreads();
    }
}

__global__ void __launch_bounds__(NTHR, 1)
kalman_lstm_kernel(const float* __restrict__ hist,
                   const float* __restrict__ mx,  const float* __restrict__ my,
                   const float* __restrict__ vsx, const float* __restrict__ asx,
                   const float* __restrict__ Rxp, const float* __restrict__ Ryp,
                   const float* __restrict__ Gx,  const float* __restrict__ Gy,
                   const float* __restrict__ WinW, const float* __restrict__ Winb,
                   const float* __restrict__ eWih, const float* __restrict__ eWhh,
                   const float* __restrict__ ebih, const float* __restrict__ ebhh,
                   const float* __restrict__ dWih, const float* __restrict__ dWhh,
                   const float* __restrict__ dbih, const float* __restrict__ dbhh,
                   const float* __restrict__ WoutW, const float* __restrict__ Woutb,
                   float* __restrict__ out)
{
    extern __shared__ char smraw[];
    SM& s = *reinterpret_cast<SM*>(smraw);
    const int tid = threadIdx.x;
    const int b0  = blockIdx.x * BT;
    const int bq  = tid & 15;
    const int dg  = tid >> 4;      // 0..31

    // ---- one-time setup ----
    pack_weights(s, tid, eWih, eWhh, ebih, ebhh);
    for (int i = tid; i < 24 * 32; i += NTHR) {
        int d = i & 31, k = i >> 5;
        s.WinT[k][d] = WinW[d * 24 + k];
    }
    if (tid < 32) s.Winb[tid] = Winb[tid];
    if (tid < 128) { int k = tid >> 2, qq = tid & 3; s.WoutT[k][qq] = WoutW[qq * 32 + k]; }
    if (tid < 4)  s.Woutb[tid] = Woutb[tid];
    for (int i = tid; i < BT * 40; i += NTHR) {
        int b = i / 40, j = i % 40;
        s.Zs[j & 1][j >> 1][b] = hist[(size_t)(b0 + b) * 40 + j];
    }
    for (int i = tid; i < 2 * 3 * 32 * BT; i += NTHR)
        (&s.Hb[0][0][0][0])[i] = 0.f;

    const float rx = Rxp[0] * Rxp[0], ry = Ryp[0] * Ryp[0];
    const float vv = vsx[0] * vsx[0], aa = asx[0] * asx[0];
    const float gxe0 = Gx[0] * mx[0], gxe1 = Gx[1] * mx[0], gxe2 = Gx[2] * mx[0];
    const float gye0 = Gy[0] * my[0], gye1 = Gy[1] * my[0], gye2 = Gy[2] * my[0];
    const float gx0 = Gx[0], gx1 = Gx[1], gx2 = Gx[2];
    const float gy0 = Gy[0], gy1 = Gy[1], gy2 = Gy[2];

    if (tid < BT) {
        int b = tid;
#pragma unroll
        for (int j = 0; j < 24; j++) s.XP[j][b] = 0.f;
        s.XP[0][b]  = hist[(size_t)(b0 + b) * 40 + 0];
        s.XP[3][b]  = hist[(size_t)(b0 + b) * 40 + 1];
        s.XP[6][b]  = rx; s.XP[10][b] = vv; s.XP[14][b] = aa;   // Px diag
        s.XP[15][b] = rx; s.XP[19][b] = vv; s.XP[23][b] = aa;   // Py diag (ref uses R_x too)
    }

    float Creg[3][4];
#pragma unroll
    for (int l = 0; l < 3; l++)
#pragma unroll
        for (int b = 0; b < 4; b++) Creg[l][b] = 0.f;

    int p = 0;
    __syncthreads();

    // ---- encoder: t = 1..19 ----
    for (int t = 1; t < TH; t++) {
        run_stack(s, bq, dg, Creg, p);
        p ^= 1;
        if (tid < 128) {
            int b = tid & 63, f = tid >> 6;
            int xo = f ? 3 : 0, po = f ? 15 : 6;
            float X[3], P[9];
#pragma unroll
            for (int i = 0; i < 3; i++) X[i] = s.XP[xo + i][b];
#pragma unroll
            for (int i = 0; i < 9; i++) P[i] = s.XP[po + i][b];
            if (f == 0) kpred_f(X, P, gxe0, gxe1, gxe2);
            else        kpred_f(X, P, gye0, gye1, gye2);
            kupd_f(X, P, s.Zs[f][t][b], f ? ry : rx);
#pragma unroll
            for (int i = 0; i < 3; i++) s.XP[xo + i][b] = X[i];
#pragma unroll
            for (int i = 0; i < 9; i++) s.XP[po + i][b] = P[i];
        }
        __syncthreads();
    }

    // ---- swap in decoder weights ----
    pack_weights(s, tid, dWih, dWhh, dbih, dbhh);
    __syncthreads();

    // ---- decoder: 30 steps ----
    for (int st = 0; st < LP; st++) {
        run_stack(s, bq, dg, Creg, p);
        p ^= 1;
        // pred = c[2] @ Wout^T + b : c[2] lives in xb[1]
        if (tid < 256) {
            int qq = tid >> 6, b = tid & 63;
            float a = s.Woutb[qq];
#pragma unroll 8
            for (int k = 0; k < 32; k++) a = fmaf(s.xb[1][k][b], s.WoutT[k][qq], a);
            s.pred[qq][b] = a;
        }
        __syncthreads();
        if (tid < 128) {
            int b = tid & 63, f = tid >> 6;
            int xo = f ? 3 : 0, po = f ? 15 : 6;
            float X[3], P[9];
#pragma unroll
            for (int i = 0; i < 3; i++) X[i] = s.XP[xo + i][b];
#pragma unroll
            for (int i = 0; i < 9; i++) P[i] = s.XP[po + i][b];
            X[2] = DTC * s.pred[f][b];
            float sc = s.pred[2 + f][b];
            float q0 = sc * (f ? gy0 : gx0);
            float q1 = sc * (f ? gy1 : gx1);
            float q2 = sc * (f ? gy2 : gx2);
            kpred_f(X, P, q0, q1, q2);
#pragma unroll
            for (int i = 0; i < 3; i++) s.XP[xo + i][b] = X[i];
#pragma unroll
            for (int i = 0; i < 9; i++) s.XP[po + i][b] = P[i];
            float* o = out + (size_t)(b0 + b) * (LP * 5) + st * 5;
            if (f == 0) { o[0] = X[0]; o[2] = sqrtf(P[0]); }
            else        { o[1] = X[0]; o[3] = sqrtf(P[0]); o[4] = 0.0f; }
        }
        __syncthreads();
    }
}

extern "C" void kernel_launch(void* const* d_in, const int* in_sizes, int n_in,
                              void* d_out, int out_size) {
    cudaFuncSetAttribute(kalman_lstm_kernel,
                         cudaFuncAttributeMaxDynamicSharedMemorySize,
                         (int)sizeof(SM));
    kalman_lstm_kernel<<<NCTA, NTHR, sizeof(SM)>>>(
        (const float*)d_in[0],  (const float*)d_in[1],  (const float*)d_in[2],
        (const float*)d_in[3],  (const float*)d_in[4],  (const float*)d_in[5],
        (const float*)d_in[6],  (const float*)d_in[7],  (const float*)d_in[8],
        (const float*)d_in[9],  (const float*)d_in[10], (const float*)d_in[11],
        (const float*)d_in[12], (const float*)d_in[13], (const float*)d_in[14],
        (const float*)d_in[15], (const float*)d_in[16], (const float*)d_in[17],
        (const float*)d_in[18], (const float*)d_in[19], (const float*)d_in[20],
        (float*)d_out);
}

// round 10
// speedup vs baseline: 1.0007x; 1.0007x over previous
#include <cuda_runtime.h>
#include <math.h>

#define BT   64
#define NCTA 128
#define NTHR 512
#define TH   20
#define LP   30
#define DTC  0.1f
#define D2C  0.005f

typedef unsigned long long ull;

struct SM {
    ulonglong2 Wp[3][64][32];   // 96KB: [l][k(0..31 x | 32..63 h)][d]: .x={Wi,Wf} .y={Wg,Wo}
    float  Hb[2][3][32][BT];    // 48KB ping-pong h
    float  xb[2][32][BT];       // 16KB ping-pong x / c
    float  XP[24][BT];          // 6KB  [Xx(3), Xy(3), Px(9), Py(9)]
    float  Zs[2][TH][BT];       // 10KB
    float  pred[4][BT];         // 1KB
    float4 bsum2[3][32];        // {bi,bf,bg,bo} per (l,d)
    float  WinT[24][32];        // Win transposed [k][d]
    float  Winb[32];
    float  WoutT[32][4];
    float  Woutb[4];
};

__device__ __forceinline__ float tanha(float x) {
    float y; asm("tanh.approx.f32 %0, %1;" : "=f"(y) : "f"(x)); return y;
}
__device__ __forceinline__ float sigm(float z) {
    return fmaf(tanha(0.5f * z), 0.5f, 0.5f);
}
__device__ __forceinline__ void ffma2(ull& a, ull w, ull x) {
    asm("fma.rn.f32x2 %0, %1, %2, %0;" : "+l"(a) : "l"(w), "l"(x));
}
__device__ __forceinline__ float2 u2f2(ull v) {
    float2 r; asm("mov.b64 {%0, %1}, %2;" : "=f"(r.x), "=f"(r.y) : "l"(v)); return r;
}
__device__ __forceinline__ ull f2u2(float lo, float hi) {
    ull r; asm("mov.b64 %0, {%1, %2};" : "=l"(r) : "f"(lo), "f"(hi)); return r;
}
__device__ __forceinline__ ull dup(float v) {
    ull r; asm("mov.b64 %0, {%1, %1};" : "=l"(r) : "f"(v)); return r;
}

__device__ __forceinline__ void pack_weights(SM& s, int tid,
        const float* __restrict__ Wih, const float* __restrict__ Whh,
        const float* __restrict__ bih, const float* __restrict__ bhh) {
    for (int i = tid; i < 3 * 64 * 32; i += NTHR) {
        int d = i & 31, kk = (i >> 5) & 63, l = i >> 11;
        const float* W = (kk < 32) ? Wih : Whh;
        int k = kk & 31;
        int base = l * 4096 + d * 32 + k;
        float4 v;
        v.x = W[base];
        v.y = W[base + 1024];
        v.z = W[base + 2048];
        v.w = W[base + 3072];
        *reinterpret_cast<float4*>(&s.Wp[l][kk][d]) = v;
    }
    for (int i = tid; i < 96; i += NTHR) {
        int l = i >> 5, d = i & 31;
        int b = l * 128 + d;
        float4 v;
        v.x = bih[b]      + bhh[b];
        v.y = bih[b + 32] + bhh[b + 32];
        v.z = bih[b + 64] + bhh[b + 64];
        v.w = bih[b + 96] + bhh[b + 96];
        s.bsum2[l][d] = v;
    }
}

// Kalman predict with Q[i][j] = g_i * g_j
__device__ __forceinline__ void kpred_f(float X[3], float P[9],
                                        float g0, float g1, float g2) {
    X[0] = X[0] + DTC * X[1] + D2C * X[2];
    X[1] = X[1] + DTC * X[2];
    float A[9];
#pragma unroll
    for (int j = 0; j < 3; j++) {
        A[0 * 3 + j] = P[0 * 3 + j] + DTC * P[1 * 3 + j] + D2C * P[2 * 3 + j];
        A[1 * 3 + j] = P[1 * 3 + j] + DTC * P[2 * 3 + j];
        A[2 * 3 + j] = P[2 * 3 + j];
    }
#pragma unroll
    for (int i = 0; i < 3; i++) {
        float qi = (i == 0) ? g0 : ((i == 1) ? g1 : g2);
        P[i * 3 + 0] = A[i * 3 + 0] + DTC * A[i * 3 + 1] + D2C * A[i * 3 + 2] + qi * g0;
        P[i * 3 + 1] = A[i * 3 + 1] + DTC * A[i * 3 + 2] + qi * g1;
        P[i * 3 + 2] = A[i * 3 + 2] + qi * g2;
    }
}

__device__ __forceinline__ void kupd_f(float X[3], float P[9], float z, float R) {
    float y = z - X[0];
    float S = P[0] + R;
    float inv = 1.0f / S;
    float K0 = P[0] * inv, K1 = P[3] * inv, K2 = P[6] * inv;
    X[0] += y * K0; X[1] += y * K1; X[2] += y * K2;
    float r0 = P[0], r1 = P[1], r2 = P[2];
    P[0] -= K0 * r0; P[1] -= K0 * r1; P[2] -= K0 * r2;
    P[3] -= K1 * r0; P[4] -= K1 * r1; P[5] -= K1 * r2;
    P[6] -= K2 * r0; P[7] -= K2 * r1; P[8] -= K2 * r2;
}

// input layer + 3 LSTM layers. Reads XP; leaves c[2] in s.xb[1].
// Thread: 1 d (dgf), 4 batch at column cb. Warp: 32 batch x 4 d -> 2 LDS wf/k.
// 4 __syncthreads.
__device__ __forceinline__ void run_stack(SM& s, int cb, int dgf, float Creg[3][4], int p) {
    // ---- input layer: x = tanh(XP @ Win^T + b) -> xb[0] ----
    {
        float acc[4];
        float bb = s.Winb[dgf];
#pragma unroll
        for (int b = 0; b < 4; b++) acc[b] = bb;
#pragma unroll 6
        for (int k = 0; k < 24; k++) {
            float4 xv = *(const float4*)&s.XP[k][cb];
            float w = s.WinT[k][dgf];
            acc[0] = fmaf(w, xv.x, acc[0]);
            acc[1] = fmaf(w, xv.y, acc[1]);
            acc[2] = fmaf(w, xv.z, acc[2]);
            acc[3] = fmaf(w, xv.w, acc[3]);
        }
        float4 r;
        r.x = tanha(acc[0]); r.y = tanha(acc[1]); r.z = tanha(acc[2]); r.w = tanha(acc[3]);
        *(float4*)&s.xb[0][dgf][cb] = r;
    }
    __syncthreads();

    // ---- 3 LSTM layers; xb ping-pong: L0: 0->1, L1: 1->0, L2: 0->1 ----
    int q = p ^ 1;
#pragma unroll 1
    for (int l = 0; l < 3; l++) {
        int ra = (l & 1);          // 0,1,0
        int wa = ra ^ 1;           // 1,0,1
        float4 bb = s.bsum2[l][dgf];
        ull aif[4], ago[4];
        {
            ull bi = f2u2(bb.x, bb.y), bg = f2u2(bb.z, bb.w);
#pragma unroll
            for (int b = 0; b < 4; b++) { aif[b] = bi; ago[b] = bg; }
        }
        const ulonglong2* __restrict__ wl = &s.Wp[l][0][0];
        const float* __restrict__ xl = &s.xb[ra][0][0];
        const float* __restrict__ hl = &s.Hb[p][l][0][0];
        // x part
#pragma unroll 4
        for (int k = 0; k < 32; k++) {
            float4 xv = *(const float4*)&xl[k * BT + cb];
            ulonglong2 w = wl[k * 32 + dgf];
            ull x0 = dup(xv.x), x1 = dup(xv.y), x2 = dup(xv.z), x3 = dup(xv.w);
            ffma2(aif[0], w.x, x0); ffma2(ago[0], w.y, x0);
            ffma2(aif[1], w.x, x1); ffma2(ago[1], w.y, x1);
            ffma2(aif[2], w.x, x2); ffma2(ago[2], w.y, x2);
            ffma2(aif[3], w.x, x3); ffma2(ago[3], w.y, x3);
        }
        // h part
#pragma unroll 4
        for (int k = 0; k < 32; k++) {
            float4 hv = *(const float4*)&hl[k * BT + cb];
            ulonglong2 w = wl[(32 + k) * 32 + dgf];
            ull x0 = dup(hv.x), x1 = dup(hv.y), x2 = dup(hv.z), x3 = dup(hv.w);
            ffma2(aif[0], w.x, x0); ffma2(ago[0], w.y, x0);
            ffma2(aif[1], w.x, x1); ffma2(ago[1], w.y, x1);
            ffma2(aif[2], w.x, x2); ffma2(ago[2], w.y, x2);
            ffma2(aif[3], w.x, x3); ffma2(ago[3], w.y, x3);
        }
        // epilogue: writes go to the OTHER buffers -> no barrier needed first
        float cn[4], hn[4];
#pragma unroll
        for (int b = 0; b < 4; b++) {
            float2 vif = u2f2(aif[b]);
            float2 vgo = u2f2(ago[b]);
            float c = fmaf(sigm(vif.y), Creg[l][b], sigm(vif.x) * tanha(vgo.x));
            float h = sigm(vgo.y) * tanha(c);
            Creg[l][b] = c;
            cn[b] = c; hn[b] = h;
        }
        float4 cv, hv;
        cv.x = cn[0]; cv.y = cn[1]; cv.z = cn[2]; cv.w = cn[3];
        hv.x = hn[0]; hv.y = hn[1]; hv.z = hn[2]; hv.w = hn[3];
        *(float4*)&s.xb[wa][dgf][cb]    = cv;
        *(float4*)&s.Hb[q][l][dgf][cb]  = hv;
        __syncthreads();
    }
}

__global__ void __launch_bounds__(NTHR, 1)
kalman_lstm_kernel(const float* __restrict__ hist,
                   const float* __restrict__ mx,  const float* __restrict__ my,
                   const float* __restrict__ vsx, const float* __restrict__ asx,
                   const float* __restrict__ Rxp, const float* __restrict__ Ryp,
                   const float* __restrict__ Gx,  const float* __restrict__ Gy,
                   const float* __restrict__ WinW, const float* __restrict__ Winb,
                   const float* __restrict__ eWih, const float* __restrict__ eWhh,
                   const float* __restrict__ ebih, const float* __restrict__ ebhh,
                   const float* __restrict__ dWih, const float* __restrict__ dWhh,
                   const float* __restrict__ dbih, const float* __restrict__ dbhh,
                   const float* __restrict__ WoutW, const float* __restrict__ Woutb,
                   float* __restrict__ out)
{
    extern __shared__ char smraw[];
    SM& s = *reinterpret_cast<SM*>(smraw);
    const int tid = threadIdx.x;
    const int b0  = blockIdx.x * BT;
    // warp = 8 batch-quads x 4 d-values, fixed batch-half & d-group:
    //   bq  = tid[0:3)   batch quad within half (0..7)
    //   dgl = tid[3:5)   d low bits (0..3)
    //   bh  = tid[5]     batch half (0..1)
    //   dgh = tid[6:9)   d high bits (0..7)
    const int bq  = tid & 7;
    const int dgl = (tid >> 3) & 3;
    const int bh  = (tid >> 5) & 1;
    const int dgh = tid >> 6;
    const int dgf = dgh * 4 + dgl;       // 0..31
    const int cb  = bh * 32 + bq * 4;    // batch column base (this thread's 4 batch)

    // ---- one-time setup ----
    pack_weights(s, tid, eWih, eWhh, ebih, ebhh);
    for (int i = tid; i < 24 * 32; i += NTHR) {
        int d = i & 31, k = i >> 5;
        s.WinT[k][d] = WinW[d * 24 + k];
    }
    if (tid < 32) s.Winb[tid] = Winb[tid];
    if (tid < 128) { int k = tid >> 2, qq = tid & 3; s.WoutT[k][qq] = WoutW[qq * 32 + k]; }
    if (tid < 4)  s.Woutb[tid] = Woutb[tid];
    for (int i = tid; i < BT * 40; i += NTHR) {
        int b = i / 40, j = i % 40;
        s.Zs[j & 1][j >> 1][b] = hist[(size_t)(b0 + b) * 40 + j];
    }
    for (int i = tid; i < 2 * 3 * 32 * BT; i += NTHR)
        (&s.Hb[0][0][0][0])[i] = 0.f;

    const float rx = Rxp[0] * Rxp[0], ry = Ryp[0] * Ryp[0];
    const float vv = vsx[0] * vsx[0], aa = asx[0] * asx[0];
    const float gxe0 = Gx[0] * mx[0], gxe1 = Gx[1] * mx[0], gxe2 = Gx[2] * mx[0];
    const float gye0 = Gy[0] * my[0], gye1 = Gy[1] * my[0], gye2 = Gy[2] * my[0];
    const float gx0 = Gx[0], gx1 = Gx[1], gx2 = Gx[2];
    const float gy0 = Gy[0], gy1 = Gy[1], gy2 = Gy[2];

    if (tid < BT) {
        int b = tid;
#pragma unroll
        for (int j = 0; j < 24; j++) s.XP[j][b] = 0.f;
        s.XP[0][b]  = hist[(size_t)(b0 + b) * 40 + 0];
        s.XP[3][b]  = hist[(size_t)(b0 + b) * 40 + 1];
        s.XP[6][b]  = rx; s.XP[10][b] = vv; s.XP[14][b] = aa;   // Px diag
        s.XP[15][b] = rx; s.XP[19][b] = vv; s.XP[23][b] = aa;   // Py diag (ref uses R_x too)
    }

    float Creg[3][4];
#pragma unroll
    for (int l = 0; l < 3; l++)
#pragma unroll
        for (int b = 0; b < 4; b++) Creg[l][b] = 0.f;

    int p = 0;
    __syncthreads();

    // ---- encoder: t = 1..19 ----
    for (int t = 1; t < TH; t++) {
        run_stack(s, cb, dgf, Creg, p);
        p ^= 1;
        if (tid < 128) {
            int b = tid & 63, f = tid >> 6;
            int xo = f ? 3 : 0, po = f ? 15 : 6;
            float X[3], P[9];
#pragma unroll
            for (int i = 0; i < 3; i++) X[i] = s.XP[xo + i][b];
#pragma unroll
            for (int i = 0; i < 9; i++) P[i] = s.XP[po + i][b];
            if (f == 0) kpred_f(X, P, gxe0, gxe1, gxe2);
            else        kpred_f(X, P, gye0, gye1, gye2);
            kupd_f(X, P, s.Zs[f][t][b], f ? ry : rx);
#pragma unroll
            for (int i = 0; i < 3; i++) s.XP[xo + i][b] = X[i];
#pragma unroll
            for (int i = 0; i < 9; i++) s.XP[po + i][b] = P[i];
        }
        __syncthreads();
    }

    // ---- swap in decoder weights ----
    pack_weights(s, tid, dWih, dWhh, dbih, dbhh);
    __syncthreads();

    // ---- decoder: 30 steps ----
    for (int st = 0; st < LP; st++) {
        run_stack(s, cb, dgf, Creg, p);
        p ^= 1;
        // pred = c[2] @ Wout^T + b : c[2] lives in xb[1]
        if (tid < 256) {
            int qq = tid >> 6, b = tid & 63;
            float a = s.Woutb[qq];
#pragma unroll 8
            for (int k = 0; k < 32; k++) a = fmaf(s.xb[1][k][b], s.WoutT[k][qq], a);
            s.pred[qq][b] = a;
        }
        __syncthreads();
        if (tid < 128) {
            int b = tid & 63, f = tid >> 6;
            int xo = f ? 3 : 0, po = f ? 15 : 6;
            float X[3], P[9];
#pragma unroll
            for (int i = 0; i < 3; i++) X[i] = s.XP[xo + i][b];
#pragma unroll
            for (int i = 0; i < 9; i++) P[i] = s.XP[po + i][b];
            X[2] = DTC * s.pred[f][b];
            float sc = s.pred[2 + f][b];
            float q0 = sc * (f ? gy0 : gx0);
            float q1 = sc * (f ? gy1 : gx1);
            float q2 = sc * (f ? gy2 : gx2);
            kpred_f(X, P, q0, q1, q2);
#pragma unroll
            for (int i = 0; i < 3; i++) s.XP[xo + i][b] = X[i];
#pragma unroll
            for (int i = 0; i < 9; i++) s.XP[po + i][b] = P[i];
            float* o = out + (size_t)(b0 + b) * (LP * 5) + st * 5;
            if (f == 0) { o[0] = X[0]; o[2] = sqrtf(P[0]); }
            else        { o[1] = X[0]; o[3] = sqrtf(P[0]); o[4] = 0.0f; }
        }
        __syncthreads();
    }
}

extern "C" void kernel_launch(void* const* d_in, const int* in_sizes, int n_in,
                              void* d_out, int out_size) {
    cudaFuncSetAttribute(kalman_lstm_kernel,
                         cudaFuncAttributeMaxDynamicSharedMemorySize,
                         (int)sizeof(SM));
    kalman_lstm_kernel<<<NCTA, NTHR, sizeof(SM)>>>(
        (const float*)d_in[0],  (const float*)d_in[1],  (const float*)d_in[2],
        (const float*)d_in[3],  (const float*)d_in[4],  (const float*)d_in[5],
        (const float*)d_in[6],  (const float*)d_in[7],  (const float*)d_in[8],
        (const float*)d_in[9],  (const float*)d_in[10], (const float*)d_in[11],
        (const float*)d_in[12], (const float*)d_in[13], (const float*)d_in[14],
        (const float*)d_in[15], (const float*)d_in[16], (const float*)d_in[17],
        (const float*)d_in[18], (const float*)d_in[19], (const float*)d_in[20],
        (float*)d_out);
}

// round 11
// speedup vs baseline: 1.1971x; 1.1962x over previous
#include <cuda_runtime.h>
#include <math.h>

#define BT   64
#define NCTA 128
#define NTHR 256
#define TH   20
#define LP   30
#define DTC  0.1f
#define D2C  0.005f

typedef unsigned long long ull;

struct SM {
    ulonglong2 Wp[3][64][32];   // 96KB: [l][k(0..31 x | 32..63 h)][d]: .x={Wi,Wf} .y={Wg,Wo}
    float  Hb[2][3][32][BT];    // 48KB ping-pong h
    float  xb[2][32][BT];       // 16KB ping-pong x / c  (L0:0->1, L1:1->0, L2:0->1)
    float  XP[24][BT];          // 6KB  [Xx(3), Xy(3), Px(9), Py(9)]
    float  Zs[2][TH][BT];       // 10KB
    float  pred[4][BT];         // 1KB
    float4 bsum2[3][32];        // {bi,bf,bg,bo} per (l,d)
    float2 Winp[24][16];        // {Win[dg][k], Win[dg+16][k]}
    float2 Winb2[16];
    float  WoutT[32][4];
    float  Woutb[4];
};

__device__ __forceinline__ float tanha(float x) {
    float y; asm("tanh.approx.f32 %0, %1;" : "=f"(y) : "f"(x)); return y;
}
__device__ __forceinline__ float sigm(float z) {
    return fmaf(tanha(0.5f * z), 0.5f, 0.5f);
}
__device__ __forceinline__ void ffma2(ull& a, ull w, ull x) {
    asm("fma.rn.f32x2 %0, %1, %2, %0;" : "+l"(a) : "l"(w), "l"(x));
}
__device__ __forceinline__ float2 u2f2(ull v) {
    float2 r; asm("mov.b64 {%0, %1}, %2;" : "=f"(r.x), "=f"(r.y) : "l"(v)); return r;
}
__device__ __forceinline__ ull f2u2(float lo, float hi) {
    ull r; asm("mov.b64 %0, {%1, %2};" : "=l"(r) : "f"(lo), "f"(hi)); return r;
}
__device__ __forceinline__ ull dup(float v) {
    ull r; asm("mov.b64 %0, {%1, %1};" : "=l"(r) : "f"(v)); return r;
}

__device__ __forceinline__ void pack_weights(SM& s, int tid,
        const float* __restrict__ Wih, const float* __restrict__ Whh,
        const float* __restrict__ bih, const float* __restrict__ bhh) {
    for (int i = tid; i < 3 * 64 * 32; i += NTHR) {
        int d = i & 31, kk = (i >> 5) & 63, l = i >> 11;
        const float* W = (kk < 32) ? Wih : Whh;
        int k = kk & 31;
        int base = l * 4096 + d * 32 + k;
        float4 v;
        v.x = W[base];
        v.y = W[base + 1024];
        v.z = W[base + 2048];
        v.w = W[base + 3072];
        *reinterpret_cast<float4*>(&s.Wp[l][kk][d]) = v;
    }
    for (int i = tid; i < 96; i += NTHR) {
        int l = i >> 5, d = i & 31;
        int b = l * 128 + d;
        float4 v;
        v.x = bih[b]      + bhh[b];
        v.y = bih[b + 32] + bhh[b + 32];
        v.z = bih[b + 64] + bhh[b + 64];
        v.w = bih[b + 96] + bhh[b + 96];
        s.bsum2[l][d] = v;
    }
}

// Kalman predict with Q[i][j] = g_i * g_j
__device__ __forceinline__ void kpred_f(float X[3], float P[9],
                                        float g0, float g1, float g2) {
    X[0] = X[0] + DTC * X[1] + D2C * X[2];
    X[1] = X[1] + DTC * X[2];
    float A[9];
#pragma unroll
    for (int j = 0; j < 3; j++) {
        A[0 * 3 + j] = P[0 * 3 + j] + DTC * P[1 * 3 + j] + D2C * P[2 * 3 + j];
        A[1 * 3 + j] = P[1 * 3 + j] + DTC * P[2 * 3 + j];
        A[2 * 3 + j] = P[2 * 3 + j];
    }
#pragma unroll
    for (int i = 0; i < 3; i++) {
        float qi = (i == 0) ? g0 : ((i == 1) ? g1 : g2);
        P[i * 3 + 0] = A[i * 3 + 0] + DTC * A[i * 3 + 1] + D2C * A[i * 3 + 2] + qi * g0;
        P[i * 3 + 1] = A[i * 3 + 1] + DTC * A[i * 3 + 2] + qi * g1;
        P[i * 3 + 2] = A[i * 3 + 2] + qi * g2;
    }
}

__device__ __forceinline__ void kupd_f(float X[3], float P[9], float z, float R) {
    float y = z - X[0];
    float S = P[0] + R;
    float inv = 1.0f / S;
    float K0 = P[0] * inv, K1 = P[3] * inv, K2 = P[6] * inv;
    X[0] += y * K0; X[1] += y * K1; X[2] += y * K2;
    float r0 = P[0], r1 = P[1], r2 = P[2];
    P[0] -= K0 * r0; P[1] -= K0 * r1; P[2] -= K0 * r2;
    P[3] -= K1 * r0; P[4] -= K1 * r1; P[5] -= K1 * r2;
    P[6] -= K2 * r0; P[7] -= K2 * r1; P[8] -= K2 * r2;
}

// input layer + 3 LSTM layers; leaves c[2] in s.xb[1]. 4 __syncthreads.
// Thread: (dg, dg+16) x 4 batch at bq*4. Warp: 16 bq x 2 dg.
__device__ __forceinline__ void run_stack(SM& s, int bq, int dg, float Creg[3][2][4], int p) {
    // ---- input layer: x = tanh(XP @ Win^T + b), paired over (dg, dg+16) -> xb[0] ----
    {
        float2 wb = s.Winb2[dg];
        ull binit = f2u2(wb.x, wb.y);
        ull acc[4];
#pragma unroll
        for (int b = 0; b < 4; b++) acc[b] = binit;
#pragma unroll 8
        for (int k = 0; k < 24; k++) {
            float4 xv = *(const float4*)&s.XP[k][bq * 4];
            ull w = *(const ull*)&s.Winp[k][dg];
            ffma2(acc[0], w, dup(xv.x));
            ffma2(acc[1], w, dup(xv.y));
            ffma2(acc[2], w, dup(xv.z));
            ffma2(acc[3], w, dup(xv.w));
        }
        float4 r0, r1;
        float2 v0 = u2f2(acc[0]), v1 = u2f2(acc[1]), v2 = u2f2(acc[2]), v3 = u2f2(acc[3]);
        r0.x = tanha(v0.x); r0.y = tanha(v1.x); r0.z = tanha(v2.x); r0.w = tanha(v3.x);
        r1.x = tanha(v0.y); r1.y = tanha(v1.y); r1.z = tanha(v2.y); r1.w = tanha(v3.y);
        *(float4*)&s.xb[0][dg][bq * 4]      = r0;
        *(float4*)&s.xb[0][dg + 16][bq * 4] = r1;
    }
    __syncthreads();

    // ---- 3 LSTM layers: accs paired over gates {i,f} and {g,o} ----
    int q = p ^ 1;
#pragma unroll 1
    for (int l = 0; l < 3; l++) {
        int ra = (l & 1);          // xb read slot: 0,1,0
        int wa = ra ^ 1;           // xb write slot: 1,0,1
        float4 b0 = s.bsum2[l][dg];
        float4 b1 = s.bsum2[l][dg + 16];
        ull aif[2][4], ago[2][4];
        {
            ull i0 = f2u2(b0.x, b0.y), g0 = f2u2(b0.z, b0.w);
            ull i1 = f2u2(b1.x, b1.y), g1 = f2u2(b1.z, b1.w);
#pragma unroll
            for (int b = 0; b < 4; b++) {
                aif[0][b] = i0; ago[0][b] = g0;
                aif[1][b] = i1; ago[1][b] = g1;
            }
        }
        const ulonglong2* __restrict__ wl = &s.Wp[l][0][0];
        const float* __restrict__ xl = &s.xb[ra][0][0];
        const float* __restrict__ hl = &s.Hb[p][l][0][0];
        // x part
#pragma unroll 8
        for (int k = 0; k < 32; k++) {
            float4 xv = *(const float4*)&xl[k * BT + bq * 4];
            ulonglong2 w0 = wl[k * 32 + dg];
            ulonglong2 w1 = wl[k * 32 + dg + 16];
            ull x0 = dup(xv.x), x1 = dup(xv.y), x2 = dup(xv.z), x3 = dup(xv.w);
            ffma2(aif[0][0], w0.x, x0); ffma2(ago[0][0], w0.y, x0);
            ffma2(aif[0][1], w0.x, x1); ffma2(ago[0][1], w0.y, x1);
            ffma2(aif[0][2], w0.x, x2); ffma2(ago[0][2], w0.y, x2);
            ffma2(aif[0][3], w0.x, x3); ffma2(ago[0][3], w0.y, x3);
            ffma2(aif[1][0], w1.x, x0); ffma2(ago[1][0], w1.y, x0);
            ffma2(aif[1][1], w1.x, x1); ffma2(ago[1][1], w1.y, x1);
            ffma2(aif[1][2], w1.x, x2); ffma2(ago[1][2], w1.y, x2);
            ffma2(aif[1][3], w1.x, x3); ffma2(ago[1][3], w1.y, x3);
        }
        // h part
#pragma unroll 8
        for (int k = 0; k < 32; k++) {
            float4 hv = *(const float4*)&hl[k * BT + bq * 4];
            ulonglong2 w0 = wl[(32 + k) * 32 + dg];
            ulonglong2 w1 = wl[(32 + k) * 32 + dg + 16];
            ull x0 = dup(hv.x), x1 = dup(hv.y), x2 = dup(hv.z), x3 = dup(hv.w);
            ffma2(aif[0][0], w0.x, x0); ffma2(ago[0][0], w0.y, x0);
            ffma2(aif[0][1], w0.x, x1); ffma2(ago[0][1], w0.y, x1);
            ffma2(aif[0][2], w0.x, x2); ffma2(ago[0][2], w0.y, x2);
            ffma2(aif[0][3], w0.x, x3); ffma2(ago[0][3], w0.y, x3);
            ffma2(aif[1][0], w1.x, x0); ffma2(ago[1][0], w1.y, x0);
            ffma2(aif[1][1], w1.x, x1); ffma2(ago[1][1], w1.y, x1);
            ffma2(aif[1][2], w1.x, x2); ffma2(ago[1][2], w1.y, x2);
            ffma2(aif[1][3], w1.x, x3); ffma2(ago[1][3], w1.y, x3);
        }
        // epilogue: writes target the OTHER buffers -> no pre-barrier needed
#pragma unroll
        for (int dp = 0; dp < 2; dp++) {
            int d = dg + 16 * dp;
            float cn[4], hn[4];
#pragma unroll
            for (int b = 0; b < 4; b++) {
                float2 vif = u2f2(aif[dp][b]);
                float2 vgo = u2f2(ago[dp][b]);
                float c = fmaf(sigm(vif.y), Creg[l][dp][b], sigm(vif.x) * tanha(vgo.x));
                float h = sigm(vgo.y) * tanha(c);
                Creg[l][dp][b] = c;
                cn[b] = c; hn[b] = h;
            }
            float4 cv, hv;
            cv.x = cn[0]; cv.y = cn[1]; cv.z = cn[2]; cv.w = cn[3];
            hv.x = hn[0]; hv.y = hn[1]; hv.z = hn[2]; hv.w = hn[3];
            *(float4*)&s.xb[wa][d][bq * 4]    = cv;
            *(float4*)&s.Hb[q][l][d][bq * 4]  = hv;
        }
        __syncthreads();
    }
}

__global__ void __launch_bounds__(NTHR, 1)
kalman_lstm_kernel(const float* __restrict__ hist,
                   const float* __restrict__ mx,  const float* __restrict__ my,
                   const float* __restrict__ vsx, const float* __restrict__ asx,
                   const float* __restrict__ Rxp, const float* __restrict__ Ryp,
                   const float* __restrict__ Gx,  const float* __restrict__ Gy,
                   const float* __restrict__ WinW, const float* __restrict__ Winb,
                   const float* __restrict__ eWih, const float* __restrict__ eWhh,
                   const float* __restrict__ ebih, const float* __restrict__ ebhh,
                   const float* __restrict__ dWih, const float* __restrict__ dWhh,
                   const float* __restrict__ dbih, const float* __restrict__ dbhh,
                   const float* __restrict__ WoutW, const float* __restrict__ Woutb,
                   float* __restrict__ out)
{
    extern __shared__ char smraw[];
    SM& s = *reinterpret_cast<SM*>(smraw);
    const int tid = threadIdx.x;
    const int b0  = blockIdx.x * BT;
    const int bq  = tid & 15;
    const int dg  = tid >> 4;     // 0..15 (handles dg and dg+16)

    // ---- one-time setup ----
    pack_weights(s, tid, eWih, eWhh, ebih, ebhh);
    for (int i = tid; i < 24 * 16; i += NTHR) {
        int k = i >> 4, dgi = i & 15;
        float2 v; v.x = WinW[dgi * 24 + k]; v.y = WinW[(dgi + 16) * 24 + k];
        s.Winp[k][dgi] = v;
    }
    if (tid < 16) { float2 v; v.x = Winb[tid]; v.y = Winb[tid + 16]; s.Winb2[tid] = v; }
    if (tid < 128) { int k = tid >> 2, qq = tid & 3; s.WoutT[k][qq] = WoutW[qq * 32 + k]; }
    if (tid < 4)  s.Woutb[tid] = Woutb[tid];
    for (int i = tid; i < BT * 40; i += NTHR) {
        int b = i / 40, j = i % 40;
        s.Zs[j & 1][j >> 1][b] = hist[(size_t)(b0 + b) * 40 + j];
    }
    for (int i = tid; i < 2 * 3 * 32 * BT; i += NTHR)
        (&s.Hb[0][0][0][0])[i] = 0.f;

    const float rx = Rxp[0] * Rxp[0], ry = Ryp[0] * Ryp[0];
    const float vv = vsx[0] * vsx[0], aa = asx[0] * asx[0];
    const float gxe0 = Gx[0] * mx[0], gxe1 = Gx[1] * mx[0], gxe2 = Gx[2] * mx[0];
    const float gye0 = Gy[0] * my[0], gye1 = Gy[1] * my[0], gye2 = Gy[2] * my[0];
    const float gx0 = Gx[0], gx1 = Gx[1], gx2 = Gx[2];
    const float gy0 = Gy[0], gy1 = Gy[1], gy2 = Gy[2];

    if (tid < BT) {
        int b = tid;
#pragma unroll
        for (int j = 0; j < 24; j++) s.XP[j][b] = 0.f;
        s.XP[0][b]  = hist[(size_t)(b0 + b) * 40 + 0];
        s.XP[3][b]  = hist[(size_t)(b0 + b) * 40 + 1];
        s.XP[6][b]  = rx; s.XP[10][b] = vv; s.XP[14][b] = aa;   // Px diag
        s.XP[15][b] = rx; s.XP[19][b] = vv; s.XP[23][b] = aa;   // Py diag (ref uses R_x too)
    }

    float Creg[3][2][4];
#pragma unroll
    for (int l = 0; l < 3; l++)
#pragma unroll
        for (int dp = 0; dp < 2; dp++)
#pragma unroll
            for (int b = 0; b < 4; b++) Creg[l][dp][b] = 0.f;

    int p = 0;
    __syncthreads();

    // ---- encoder: t = 1..19 ----
    for (int t = 1; t < TH; t++) {
        run_stack(s, bq, dg, Creg, p);
        p ^= 1;
        if (tid < 128) {
            int b = tid & 63, f = tid >> 6;
            int xo = f ? 3 : 0, po = f ? 15 : 6;
            float X[3], P[9];
#pragma unroll
            for (int i = 0; i < 3; i++) X[i] = s.XP[xo + i][b];
#pragma unroll
            for (int i = 0; i < 9; i++) P[i] = s.XP[po + i][b];
            if (f == 0) kpred_f(X, P, gxe0, gxe1, gxe2);
            else        kpred_f(X, P, gye0, gye1, gye2);
            kupd_f(X, P, s.Zs[f][t][b], f ? ry : rx);
#pragma unroll
            for (int i = 0; i < 3; i++) s.XP[xo + i][b] = X[i];
#pragma unroll
            for (int i = 0; i < 9; i++) s.XP[po + i][b] = P[i];
        }
        __syncthreads();
    }

    // ---- swap in decoder weights ----
    pack_weights(s, tid, dWih, dWhh, dbih, dbhh);
    __syncthreads();

    // ---- decoder: 30 steps ----
    for (int st = 0; st < LP; st++) {
        run_stack(s, bq, dg, Creg, p);
        p ^= 1;
        // pred = c[2] @ Wout^T + b : c[2] lives in xb[1]
        {
            int qq = tid >> 6, b = tid & 63;
            float a = s.Woutb[qq];
#pragma unroll 8
            for (int k = 0; k < 32; k++) a = fmaf(s.xb[1][k][b], s.WoutT[k][qq], a);
            s.pred[qq][b] = a;
        }
        __syncthreads();
        if (tid < 128) {
            int b = tid & 63, f = tid >> 6;
            int xo = f ? 3 : 0, po = f ? 15 : 6;
            float X[3], P[9];
#pragma unroll
            for (int i = 0; i < 3; i++) X[i] = s.XP[xo + i][b];
#pragma unroll
            for (int i = 0; i < 9; i++) P[i] = s.XP[po + i][b];
            X[2] = DTC * s.pred[f][b];
            float sc = s.pred[2 + f][b];
            float q0 = sc * (f ? gy0 : gx0);
            float q1 = sc * (f ? gy1 : gx1);
            float q2 = sc * (f ? gy2 : gx2);
            kpred_f(X, P, q0, q1, q2);
#pragma unroll
            for (int i = 0; i < 3; i++) s.XP[xo + i][b] = X[i];
#pragma unroll
            for (int i = 0; i < 9; i++) s.XP[po + i][b] = P[i];
            float* o = out + (size_t)(b0 + b) * (LP * 5) + st * 5;
            if (f == 0) { o[0] = X[0]; o[2] = sqrtf(P[0]); }
            else        { o[1] = X[0]; o[3] = sqrtf(P[0]); o[4] = 0.0f; }
        }
        __syncthreads();
    }
}

extern "C" void kernel_launch(void* const* d_in, const int* in_sizes, int n_in,
                              void* d_out, int out_size) {
    cudaFuncSetAttribute(kalman_lstm_kernel,
                         cudaFuncAttributeMaxDynamicSharedMemorySize,
                         (int)sizeof(SM));
    kalman_lstm_kernel<<<NCTA, NTHR, sizeof(SM)>>>(
        (const float*)d_in[0],  (const float*)d_in[1],  (const float*)d_in[2],
        (const float*)d_in[3],  (const float*)d_in[4],  (const float*)d_in[5],
        (const float*)d_in[6],  (const float*)d_in[7],  (const float*)d_in[8],
        (const float*)d_in[9],  (const float*)d_in[10], (const float*)d_in[11],
        (const float*)d_in[12], (const float*)d_in[13], (const float*)d_in[14],
        (const float*)d_in[15], (const float*)d_in[16], (const float*)d_in[17],
        (const float*)d_in[18], (const float*)d_in[19], (const float*)d_in[20],
        (float*)d_out);
}

// round 13
// speedup vs baseline: 1.7933x; 1.4981x over previous
#include <cuda_runtime.h>
#include <cuda_bf16.h>
#include <math.h>

typedef unsigned int u32;

#define BT   64
#define NCTA 128
#define NTHR 256
#define TH   20
#define LP   30
#define DTC  0.1f
#define D2C  0.005f
#define PADK 72     // bf16 elems per row in W/X tiles (bank = 4g+tg, conflict-free)
#define GPAD 132    // floats per row of gate stage [n][m]

struct __align__(16) SM {
    __nv_bfloat16 Wt[3][2][128 * PADK];  // 110.6KB [layer][hi/lo][m][k] k=[x32|h32]
    __nv_bfloat16 Xt[3][2][64 * PADK];   // 55.3KB  [layer][hi/lo][n][k] x cols 0..31, h cols 32..63
    float Gf[64][GPAD];                  // 33.8KB  gates staged [n][m]
    float c2f[32][64];                   // 8KB
    float XP[24][64];                    // 6KB
    float Zs[2][TH][64];                 // 10KB
    float pred[4][64];
    float bsum[3][128];
    float WinT[24][32];
    float Winb[32];
    float WoutT[32][4];
    float Woutb[4];
};

__device__ __forceinline__ float tanha(float x) {
    float y; asm("tanh.approx.f32 %0, %1;" : "=f"(y) : "f"(x)); return y;
}
__device__ __forceinline__ float sigm(float z) { return fmaf(tanha(0.5f * z), 0.5f, 0.5f); }
__device__ __forceinline__ u32 pkbf(float lo, float hi) {  // lower 16 = lo, upper 16 = hi
    u32 r; asm("cvt.rn.bf16x2.f32 %0, %1, %2;" : "=r"(r) : "f"(hi), "f"(lo)); return r;
}
__device__ __forceinline__ void mma16816(float* d, const u32* a, u32 b0, u32 b1) {
    asm volatile("mma.sync.aligned.m16n8k16.row.col.f32.bf16.bf16.f32 "
        "{%0,%1,%2,%3}, {%4,%5,%6,%7}, {%8,%9}, {%0,%1,%2,%3};"
        : "+f"(d[0]), "+f"(d[1]), "+f"(d[2]), "+f"(d[3])
        : "r"(a[0]), "r"(a[1]), "r"(a[2]), "r"(a[3]), "r"(b0), "r"(b1));
}

__device__ __forceinline__ void pack_wts(SM& s, int tid,
        const float* __restrict__ Wih, const float* __restrict__ Whh,
        const float* __restrict__ bih, const float* __restrict__ bhh) {
    for (int i = tid; i < 3 * 128 * 64; i += NTHR) {
        int l = i >> 13, r = i & 8191, m = r >> 6, k = r & 63;
        float v = (k < 32) ? Wih[l * 4096 + m * 32 + k] : Whh[l * 4096 + m * 32 + (k - 32)];
        __nv_bfloat16 h = __float2bfloat16(v);
        s.Wt[l][0][m * PADK + k] = h;
        s.Wt[l][1][m * PADK + k] = __float2bfloat16(v - __bfloat162float(h));
    }
    for (int i = tid; i < 384; i += NTHR)
        ((float*)s.bsum)[i] = bih[i] + bhh[i];
}

__device__ __forceinline__ void kpred_f(float X[3], float P[9], float g0, float g1, float g2) {
    X[0] = X[0] + DTC * X[1] + D2C * X[2];
    X[1] = X[1] + DTC * X[2];
    float A[9];
#pragma unroll
    for (int j = 0; j < 3; j++) {
        A[0 * 3 + j] = P[0 * 3 + j] + DTC * P[1 * 3 + j] + D2C * P[2 * 3 + j];
        A[1 * 3 + j] = P[1 * 3 + j] + DTC * P[2 * 3 + j];
        A[2 * 3 + j] = P[2 * 3 + j];
    }
#pragma unroll
    for (int i = 0; i < 3; i++) {
        float qi = (i == 0) ? g0 : ((i == 1) ? g1 : g2);
        P[i * 3 + 0] = A[i * 3 + 0] + DTC * A[i * 3 + 1] + D2C * A[i * 3 + 2] + qi * g0;
        P[i * 3 + 1] = A[i * 3 + 1] + DTC * A[i * 3 + 2] + qi * g1;
        P[i * 3 + 2] = A[i * 3 + 2] + qi * g2;
    }
}
__device__ __forceinline__ void kupd_f(float X[3], float P[9], float z, float R) {
    float y = z - X[0];
    float S = P[0] + R;
    float inv = 1.0f / S;
    float K0 = P[0] * inv, K1 = P[3] * inv, K2 = P[6] * inv;
    X[0] += y * K0; X[1] += y * K1; X[2] += y * K2;
    float r0 = P[0], r1 = P[1], r2 = P[2];
    P[0] -= K0 * r0; P[1] -= K0 * r1; P[2] -= K0 * r2;
    P[3] -= K1 * r0; P[4] -= K1 * r1; P[5] -= K1 * r2;
    P[6] -= K2 * r0; P[7] -= K2 * r1; P[8] -= K2 * r2;
}

// input layer: x[b][d0..d0+7] = tanh(XP[.][b] @ Win^T + b) -> Xt[0] hi/lo
__device__ __forceinline__ void input_layer(SM& s, int b, int d0) {
    float acc[8];
    *(float4*)&acc[0] = *(const float4*)&s.Winb[d0];
    *(float4*)&acc[4] = *(const float4*)&s.Winb[d0 + 4];
#pragma unroll
    for (int k = 0; k < 24; k++) {
        float xv = s.XP[k][b];
        float4 w0 = *(const float4*)&s.WinT[k][d0];
        float4 w1 = *(const float4*)&s.WinT[k][d0 + 4];
        acc[0] = fmaf(w0.x, xv, acc[0]); acc[1] = fmaf(w0.y, xv, acc[1]);
        acc[2] = fmaf(w0.z, xv, acc[2]); acc[3] = fmaf(w0.w, xv, acc[3]);
        acc[4] = fmaf(w1.x, xv, acc[4]); acc[5] = fmaf(w1.y, xv, acc[5]);
        acc[6] = fmaf(w1.z, xv, acc[6]); acc[7] = fmaf(w1.w, xv, acc[7]);
    }
    float xh[8], xl[8];
#pragma unroll
    for (int j = 0; j < 8; j++) {
        float x = tanha(acc[j]);
        float h = __bfloat162float(__float2bfloat16(x));
        xh[j] = h; xl[j] = x - h;
    }
    uint4 qh, ql;
    qh.x = pkbf(xh[0], xh[1]); qh.y = pkbf(xh[2], xh[3]);
    qh.z = pkbf(xh[4], xh[5]); qh.w = pkbf(xh[6], xh[7]);
    ql.x = pkbf(xl[0], xl[1]); ql.y = pkbf(xl[2], xl[3]);
    ql.z = pkbf(xl[4], xl[5]); ql.w = pkbf(xl[6], xl[7]);
    *(uint4*)&s.Xt[0][0][b * PADK + d0] = qh;
    *(uint4*)&s.Xt[0][1][b * PADK + d0] = ql;
}

// one layer GEMM: Gf[n][m] = sum_k W[m][k] X[n][k] via hi/lo bf16 mma.sync
__device__ __forceinline__ void do_layer_mma(SM& s, int l, int wid, int lane) {
    const int g = lane >> 2, tg = lane & 3;
    const int mrow = wid * 16 + g;
    const __nv_bfloat16* __restrict__ W0 = &s.Wt[l][0][0];
    const __nv_bfloat16* __restrict__ W1 = &s.Wt[l][1][0];
    const __nv_bfloat16* __restrict__ X0 = &s.Xt[l][0][0];
    const __nv_bfloat16* __restrict__ X1 = &s.Xt[l][1][0];
    float D[8][4];
#pragma unroll
    for (int nt = 0; nt < 8; nt++)
#pragma unroll
        for (int j = 0; j < 4; j++) D[nt][j] = 0.f;
#pragma unroll
    for (int ks = 0; ks < 4; ks++) {
        const int k0 = ks * 16 + 2 * tg;
        u32 ah[4], al[4];
        ah[0] = *(const u32*)&W0[mrow * PADK + k0];
        ah[1] = *(const u32*)&W0[(mrow + 8) * PADK + k0];
        ah[2] = *(const u32*)&W0[mrow * PADK + k0 + 8];
        ah[3] = *(const u32*)&W0[(mrow + 8) * PADK + k0 + 8];
        al[0] = *(const u32*)&W1[mrow * PADK + k0];
        al[1] = *(const u32*)&W1[(mrow + 8) * PADK + k0];
        al[2] = *(const u32*)&W1[mrow * PADK + k0 + 8];
        al[3] = *(const u32*)&W1[(mrow + 8) * PADK + k0 + 8];
#pragma unroll
        for (int nt = 0; nt < 8; nt++) {
            const int n = nt * 8 + g;
            u32 bh0 = *(const u32*)&X0[n * PADK + k0];
            u32 bh1 = *(const u32*)&X0[n * PADK + k0 + 8];
            u32 bl0 = *(const u32*)&X1[n * PADK + k0];
            u32 bl1 = *(const u32*)&X1[n * PADK + k0 + 8];
            mma16816(D[nt], ah, bh0, bh1);
            mma16816(D[nt], ah, bl0, bl1);
            mma16816(D[nt], al, bh0, bh1);
        }
    }
    // stage: D[m=mrow(+8)][n=nt*8+2tg(+1)] -> Gf[n][m]  (bank 8tg+g+16w: conflict-free)
#pragma unroll
    for (int nt = 0; nt < 8; nt++) {
        const int n = nt * 8 + 2 * tg;
        s.Gf[n][mrow]         = D[nt][0];
        s.Gf[n + 1][mrow]     = D[nt][1];
        s.Gf[n][mrow + 8]     = D[nt][2];
        s.Gf[n + 1][mrow + 8] = D[nt][3];
    }
}

// epilogue: gates(+bias) -> c,h -> bf16 hi/lo tiles; thread owns (b, d0..d0+7)
__device__ __forceinline__ void epilogue(SM& s, int l, int b, int d0, float* C) {
    float gi[8], gf_[8], gg[8], go[8];
    *(float4*)&gi[0]  = *(const float4*)&s.Gf[b][d0];
    *(float4*)&gi[4]  = *(const float4*)&s.Gf[b][d0 + 4];
    *(float4*)&gf_[0] = *(const float4*)&s.Gf[b][32 + d0];
    *(float4*)&gf_[4] = *(const float4*)&s.Gf[b][32 + d0 + 4];
    *(float4*)&gg[0]  = *(const float4*)&s.Gf[b][64 + d0];
    *(float4*)&gg[4]  = *(const float4*)&s.Gf[b][64 + d0 + 4];
    *(float4*)&go[0]  = *(const float4*)&s.Gf[b][96 + d0];
    *(float4*)&go[4]  = *(const float4*)&s.Gf[b][96 + d0 + 4];
    const float* bb = &s.bsum[l][0];
    float bi[8], bf2[8], bg[8], bo[8];
    *(float4*)&bi[0]  = *(const float4*)(bb + d0);      *(float4*)&bi[4]  = *(const float4*)(bb + d0 + 4);
    *(float4*)&bf2[0] = *(const float4*)(bb + 32 + d0); *(float4*)&bf2[4] = *(const float4*)(bb + 32 + d0 + 4);
    *(float4*)&bg[0]  = *(const float4*)(bb + 64 + d0); *(float4*)&bg[4]  = *(const float4*)(bb + 64 + d0 + 4);
    *(float4*)&bo[0]  = *(const float4*)(bb + 96 + d0); *(float4*)&bo[4]  = *(const float4*)(bb + 96 + d0 + 4);
    float ch[8], cl[8], hh[8], hl[8];
#pragma unroll
    for (int j = 0; j < 8; j++) {
        float c = fmaf(sigm(gf_[j] + bf2[j]), C[j], sigm(gi[j] + bi[j]) * tanha(gg[j] + bg[j]));
        float h = sigm(go[j] + bo[j]) * tanha(c);
        C[j] = c;
        float chi = __bfloat162float(__float2bfloat16(c));
        float hhi = __bfloat162float(__float2bfloat16(h));
        ch[j] = chi; cl[j] = c - chi;
        hh[j] = hhi; hl[j] = h - hhi;
        if (l == 2) s.c2f[d0 + j][b] = c;
    }
    uint4 q;
    q.x = pkbf(hh[0], hh[1]); q.y = pkbf(hh[2], hh[3]);
    q.z = pkbf(hh[4], hh[5]); q.w = pkbf(hh[6], hh[7]);
    *(uint4*)&s.Xt[l][0][b * PADK + 32 + d0] = q;
    q.x = pkbf(hl[0], hl[1]); q.y = pkbf(hl[2], hl[3]);
    q.z = pkbf(hl[4], hl[5]); q.w = pkbf(hl[6], hl[7]);
    *(uint4*)&s.Xt[l][1][b * PADK + 32 + d0] = q;
    if (l < 2) {
        q.x = pkbf(ch[0], ch[1]); q.y = pkbf(ch[2], ch[3]);
        q.z = pkbf(ch[4], ch[5]); q.w = pkbf(ch[6], ch[7]);
        *(uint4*)&s.Xt[l + 1][0][b * PADK + d0] = q;
        q.x = pkbf(cl[0], cl[1]); q.y = pkbf(cl[2], cl[3]);
        q.z = pkbf(cl[4], cl[5]); q.w = pkbf(cl[6], cl[7]);
        *(uint4*)&s.Xt[l + 1][1][b * PADK + d0] = q;
    }
}

__global__ void __launch_bounds__(NTHR, 1)
kalman_lstm_kernel(const float* __restrict__ hist,
                   const float* __restrict__ mx,  const float* __restrict__ my,
                   const float* __restrict__ vsx, const float* __restrict__ asx,
                   const float* __restrict__ Rxp, const float* __restrict__ Ryp,
                   const float* __restrict__ Gx,  const float* __restrict__ Gy,
                   const float* __restrict__ WinW, const float* __restrict__ Winb,
                   const float* __restrict__ eWih, const float* __restrict__ eWhh,
                   const float* __restrict__ ebih, const float* __restrict__ ebhh,
                   const float* __restrict__ dWih, const float* __restrict__ dWhh,
                   const float* __restrict__ dbih, const float* __restrict__ dbhh,
                   const float* __restrict__ WoutW, const float* __restrict__ Woutb,
                   float* __restrict__ out)
{
    extern __shared__ char smraw[];
    SM& s = *reinterpret_cast<SM*>(smraw);
    const int tid  = threadIdx.x;
    const int wid  = tid >> 5, lane = tid & 31;
    const int b0   = blockIdx.x * BT;
    const int b    = tid & 63;
    const int d0   = (tid >> 6) * 8;

    // ---- one-time setup ----
    pack_wts(s, tid, eWih, eWhh, ebih, ebhh);
    for (int i = tid; i < 24 * 32; i += NTHR) {
        int d = i & 31, k = i >> 5;
        s.WinT[k][d] = WinW[d * 24 + k];
    }
    if (tid < 32) s.Winb[tid] = Winb[tid];
    if (tid < 128) { int k = tid >> 2, qq = tid & 3; s.WoutT[k][qq] = WoutW[qq * 32 + k]; }
    if (tid < 4)  s.Woutb[tid] = Woutb[tid];
    for (int i = tid; i < BT * 40; i += NTHR) {
        int bb2 = i / 40, j = i % 40;
        s.Zs[j & 1][j >> 1][bb2] = hist[(size_t)(b0 + bb2) * 40 + j];
    }
    for (int i = tid; i < (int)(sizeof(s.Xt) / 4); i += NTHR)
        ((u32*)&s.Xt[0][0][0])[i] = 0u;

    const float rx = Rxp[0] * Rxp[0], ry = Ryp[0] * Ryp[0];
    const float vv = vsx[0] * vsx[0], aa = asx[0] * asx[0];
    const float gxe0 = Gx[0] * mx[0], gxe1 = Gx[1] * mx[0], gxe2 = Gx[2] * mx[0];
    const float gye0 = Gy[0] * my[0], gye1 = Gy[1] * my[0], gye2 = Gy[2] * my[0];
    const float gx0 = Gx[0], gx1 = Gx[1], gx2 = Gx[2];
    const float gy0 = Gy[0], gy1 = Gy[1], gy2 = Gy[2];

    if (tid < BT) {
#pragma unroll
        for (int j = 0; j < 24; j++) s.XP[j][tid] = 0.f;
        s.XP[0][tid]  = hist[(size_t)(b0 + tid) * 40 + 0];
        s.XP[3][tid]  = hist[(size_t)(b0 + tid) * 40 + 1];
        s.XP[6][tid]  = rx; s.XP[10][tid] = vv; s.XP[14][tid] = aa;
        s.XP[15][tid] = rx; s.XP[19][tid] = vv; s.XP[23][tid] = aa;
    }

    float Creg[3][8];
#pragma unroll
    for (int l = 0; l < 3; l++)
#pragma unroll
        for (int j = 0; j < 8; j++) Creg[l][j] = 0.f;

    __syncthreads();

    // ================= encoder: t = 1..19 =================
    for (int t = 1; t < TH; t++) {
        input_layer(s, b, d0);
        __syncthreads();
#pragma unroll 1
        for (int l = 0; l < 3; l++) {
            do_layer_mma(s, l, wid, lane);
            __syncthreads();
            epilogue(s, l, b, d0, Creg[l]);
            __syncthreads();
        }
        if (tid < 128) {
            int bb2 = tid & 63, f = tid >> 6;
            int xo = f ? 3 : 0, po = f ? 15 : 6;
            float X[3], P[9];
#pragma unroll
            for (int i = 0; i < 3; i++) X[i] = s.XP[xo + i][bb2];
#pragma unroll
            for (int i = 0; i < 9; i++) P[i] = s.XP[po + i][bb2];
            if (f == 0) kpred_f(X, P, gxe0, gxe1, gxe2);
            else        kpred_f(X, P, gye0, gye1, gye2);
            kupd_f(X, P, s.Zs[f][t][bb2], f ? ry : rx);
#pragma unroll
            for (int i = 0; i < 3; i++) s.XP[xo + i][bb2] = X[i];
#pragma unroll
            for (int i = 0; i < 9; i++) s.XP[po + i][bb2] = P[i];
        }
        __syncthreads();
    }

    // ---- swap in decoder weights ----
    pack_wts(s, tid, dWih, dWhh, dbih, dbhh);
    __syncthreads();

    // ================= decoder: 30 steps =================
    for (int st = 0; st < LP; st++) {
        input_layer(s, b, d0);
        __syncthreads();
#pragma unroll 1
        for (int l = 0; l < 3; l++) {
            do_layer_mma(s, l, wid, lane);
            __syncthreads();
            epilogue(s, l, b, d0, Creg[l]);
            __syncthreads();
        }
        // pred = c2 @ Wout^T + b
        {
            int qq = tid >> 6, bb2 = tid & 63;
            float a = s.Woutb[qq];
#pragma unroll 8
            for (int k = 0; k < 32; k++) a = fmaf(s.c2f[k][bb2], s.WoutT[k][qq], a);
            s.pred[qq][bb2] = a;
        }
        __syncthreads();
        if (tid < 128) {
            int bb2 = tid & 63, f = tid >> 6;
            int xo = f ? 3 : 0, po = f ? 15 : 6;
            float X[3], P[9];
#pragma unroll
            for (int i = 0; i < 3; i++) X[i] = s.XP[xo + i][bb2];
#pragma unroll
            for (int i = 0; i < 9; i++) P[i] = s.XP[po + i][bb2];
            X[2] = DTC * s.pred[f][bb2];
            float sc = s.pred[2 + f][bb2];
            float q0 = sc * (f ? gy0 : gx0);
            float q1 = sc * (f ? gy1 : gx1);
            float q2 = sc * (f ? gy2 : gx2);
            kpred_f(X, P, q0, q1, q2);
#pragma unroll
            for (int i = 0; i < 3; i++) s.XP[xo + i][bb2] = X[i];
#pragma unroll
            for (int i = 0; i < 9; i++) s.XP[po + i][bb2] = P[i];
            float* o = out + (size_t)(b0 + bb2) * (LP * 5) + st * 5;
            if (f == 0) { o[0] = X[0]; o[2] = sqrtf(P[0]); }
            else        { o[1] = X[0]; o[3] = sqrtf(P[0]); o[4] = 0.0f; }
        }
        __syncthreads();
    }
}

extern "C" void kernel_launch(void* const* d_in, const int* in_sizes, int n_in,
                              void* d_out, int out_size) {
    cudaFuncSetAttribute(kalman_lstm_kernel,
                         cudaFuncAttributeMaxDynamicSharedMemorySize,
                         (int)sizeof(SM));
    kalman_lstm_kernel<<<NCTA, NTHR, sizeof(SM)>>>(
        (const float*)d_in[0],  (const float*)d_in[1],  (const float*)d_in[2],
        (const float*)d_in[3],  (const float*)d_in[4],  (const float*)d_in[5],
        (const float*)d_in[6],  (const float*)d_in[7],  (const float*)d_in[8],
        (const float*)d_in[9],  (const float*)d_in[10], (const float*)d_in[11],
        (const float*)d_in[12], (const float*)d_in[13], (const float*)d_in[14],
        (const float*)d_in[15], (const float*)d_in[16], (const float*)d_in[17],
        (const float*)d_in[18], (const float*)d_in[19], (const float*)d_in[20],
        (float*)d_out);
}

// round 14
// speedup vs baseline: 1.8405x; 1.0263x over previous
#include <cuda_runtime.h>
#include <cuda_bf16.h>
#include <math.h>

typedef unsigned int u32;

#define BT   64
#define NCTA 128
#define NTHR 256
#define TH   20
#define LP   30
#define DTC  0.1f
#define D2C  0.005f
#define PADK 72     // bf16 elems per row in W/X tiles (bank = 4g+tg, conflict-free)
#define GPAD 132    // floats per row of gate stage [n][m]

struct __align__(16) SM {
    __nv_bfloat16 Wt[3][2][128 * PADK];  // 110.6KB [layer][hi/lo][m][k] k=[x32|h32]
    __nv_bfloat16 Xt[3][2][64 * PADK];   // 55.3KB  [layer][hi/lo][n][k] x cols 0..31, h cols 32..63
    float Gf[64][GPAD];                  // 33.8KB  gates staged [n][m]
    float c2f[32][64];                   // 8KB
    float XP[24][64];                    // 6KB
    float Zs[2][TH][64];                 // 10KB
    float pred[4][64];
    float bsum[3][128];
    float WinT[24][32];
    float Winb[32];
    float WoutT[32][4];
    float Woutb[4];
};

__device__ __forceinline__ void barg(int g) {   // per-group named barrier, 128 threads
    asm volatile("bar.sync %0, %1;" :: "r"(g + 1), "r"(128) : "memory");
}
__device__ __forceinline__ float tanha(float x) {
    float y; asm("tanh.approx.f32 %0, %1;" : "=f"(y) : "f"(x)); return y;
}
__device__ __forceinline__ float sigm(float z) { return fmaf(tanha(0.5f * z), 0.5f, 0.5f); }
__device__ __forceinline__ u32 pkbf(float lo, float hi) {
    u32 r; asm("cvt.rn.bf16x2.f32 %0, %1, %2;" : "=r"(r) : "f"(hi), "f"(lo)); return r;
}
__device__ __forceinline__ void mma16816(float* d, const u32* a, u32 b0, u32 b1) {
    asm volatile("mma.sync.aligned.m16n8k16.row.col.f32.bf16.bf16.f32 "
        "{%0,%1,%2,%3}, {%4,%5,%6,%7}, {%8,%9}, {%0,%1,%2,%3};"
        : "+f"(d[0]), "+f"(d[1]), "+f"(d[2]), "+f"(d[3])
        : "r"(a[0]), "r"(a[1]), "r"(a[2]), "r"(a[3]), "r"(b0), "r"(b1));
}

__device__ __forceinline__ void pack_wts(SM& s, int tid,
        const float* __restrict__ Wih, const float* __restrict__ Whh,
        const float* __restrict__ bih, const float* __restrict__ bhh) {
    for (int i = tid; i < 3 * 128 * 64; i += NTHR) {
        int l = i >> 13, r = i & 8191, m = r >> 6, k = r & 63;
        float v = (k < 32) ? Wih[l * 4096 + m * 32 + k] : Whh[l * 4096 + m * 32 + (k - 32)];
        __nv_bfloat16 h = __float2bfloat16(v);
        s.Wt[l][0][m * PADK + k] = h;
        s.Wt[l][1][m * PADK + k] = __float2bfloat16(v - __bfloat162float(h));
    }
    for (int i = tid; i < 384; i += NTHR)
        ((float*)s.bsum)[i] = bih[i] + bhh[i];
}

__device__ __forceinline__ void kpred_f(float X[3], float P[9], float g0, float g1, float g2) {
    X[0] = X[0] + DTC * X[1] + D2C * X[2];
    X[1] = X[1] + DTC * X[2];
    float A[9];
#pragma unroll
    for (int j = 0; j < 3; j++) {
        A[0 * 3 + j] = P[0 * 3 + j] + DTC * P[1 * 3 + j] + D2C * P[2 * 3 + j];
        A[1 * 3 + j] = P[1 * 3 + j] + DTC * P[2 * 3 + j];
        A[2 * 3 + j] = P[2 * 3 + j];
    }
#pragma unroll
    for (int i = 0; i < 3; i++) {
        float qi = (i == 0) ? g0 : ((i == 1) ? g1 : g2);
        P[i * 3 + 0] = A[i * 3 + 0] + DTC * A[i * 3 + 1] + D2C * A[i * 3 + 2] + qi * g0;
        P[i * 3 + 1] = A[i * 3 + 1] + DTC * A[i * 3 + 2] + qi * g1;
        P[i * 3 + 2] = A[i * 3 + 2] + qi * g2;
    }
}
__device__ __forceinline__ void kupd_f(float X[3], float P[9], float z, float R) {
    float y = z - X[0];
    float S = P[0] + R;
    float inv = 1.0f / S;
    float K0 = P[0] * inv, K1 = P[3] * inv, K2 = P[6] * inv;
    X[0] += y * K0; X[1] += y * K1; X[2] += y * K2;
    float r0 = P[0], r1 = P[1], r2 = P[2];
    P[0] -= K0 * r0; P[1] -= K0 * r1; P[2] -= K0 * r2;
    P[3] -= K1 * r0; P[4] -= K1 * r1; P[5] -= K1 * r2;
    P[6] -= K2 * r0; P[7] -= K2 * r1; P[8] -= K2 * r2;
}

// input layer: x[b][d0..d0+7] = tanh(XP[.][b] @ Win^T + b) -> Xt[0] hi/lo
__device__ __forceinline__ void input_layer(SM& s, int b, int d0) {
    float acc[8];
    *(float4*)&acc[0] = *(const float4*)&s.Winb[d0];
    *(float4*)&acc[4] = *(const float4*)&s.Winb[d0 + 4];
#pragma unroll
    for (int k = 0; k < 24; k++) {
        float xv = s.XP[k][b];
        float4 w0 = *(const float4*)&s.WinT[k][d0];
        float4 w1 = *(const float4*)&s.WinT[k][d0 + 4];
        acc[0] = fmaf(w0.x, xv, acc[0]); acc[1] = fmaf(w0.y, xv, acc[1]);
        acc[2] = fmaf(w0.z, xv, acc[2]); acc[3] = fmaf(w0.w, xv, acc[3]);
        acc[4] = fmaf(w1.x, xv, acc[4]); acc[5] = fmaf(w1.y, xv, acc[5]);
        acc[6] = fmaf(w1.z, xv, acc[6]); acc[7] = fmaf(w1.w, xv, acc[7]);
    }
    float xh[8], xl[8];
#pragma unroll
    for (int j = 0; j < 8; j++) {
        float x = tanha(acc[j]);
        float h = __bfloat162float(__float2bfloat16(x));
        xh[j] = h; xl[j] = x - h;
    }
    uint4 qh, ql;
    qh.x = pkbf(xh[0], xh[1]); qh.y = pkbf(xh[2], xh[3]);
    qh.z = pkbf(xh[4], xh[5]); qh.w = pkbf(xh[6], xh[7]);
    ql.x = pkbf(xl[0], xl[1]); ql.y = pkbf(xl[2], xl[3]);
    ql.z = pkbf(xl[4], xl[5]); ql.w = pkbf(xl[6], xl[7]);
    *(uint4*)&s.Xt[0][0][b * PADK + d0] = qh;
    *(uint4*)&s.Xt[0][1][b * PADK + d0] = ql;
}

// group-half GEMM: Gf[n][m] += W[m][k] X[n][k], n in [g*32, g*32+32), all m 0..127.
// Local warp w0 (0..3) covers m-tiles at w0*16 and w0*16+64. B frags shared across m-tiles.
__device__ __forceinline__ void do_layer_mma(SM& s, int l, int w0, int lane, int g) {
    const int g8 = lane >> 2, tg = lane & 3;
    const int n_base = g * 32;
    const __nv_bfloat16* __restrict__ W0 = &s.Wt[l][0][0];
    const __nv_bfloat16* __restrict__ W1 = &s.Wt[l][1][0];
    const __nv_bfloat16* __restrict__ X0 = &s.Xt[l][0][0];
    const __nv_bfloat16* __restrict__ X1 = &s.Xt[l][1][0];
    float D[2][4][4];
#pragma unroll
    for (int mt = 0; mt < 2; mt++)
#pragma unroll
        for (int nt = 0; nt < 4; nt++)
#pragma unroll
            for (int j = 0; j < 4; j++) D[mt][nt][j] = 0.f;
#pragma unroll
    for (int ks = 0; ks < 4; ks++) {
        const int k0 = ks * 16 + 2 * tg;
        u32 ah[2][4], al[2][4];
#pragma unroll
        for (int mt = 0; mt < 2; mt++) {
            const int mrow = w0 * 16 + mt * 64 + g8;
            ah[mt][0] = *(const u32*)&W0[mrow * PADK + k0];
            ah[mt][1] = *(const u32*)&W0[(mrow + 8) * PADK + k0];
            ah[mt][2] = *(const u32*)&W0[mrow * PADK + k0 + 8];
            ah[mt][3] = *(const u32*)&W0[(mrow + 8) * PADK + k0 + 8];
            al[mt][0] = *(const u32*)&W1[mrow * PADK + k0];
            al[mt][1] = *(const u32*)&W1[(mrow + 8) * PADK + k0];
            al[mt][2] = *(const u32*)&W1[mrow * PADK + k0 + 8];
            al[mt][3] = *(const u32*)&W1[(mrow + 8) * PADK + k0 + 8];
        }
#pragma unroll
        for (int nt = 0; nt < 4; nt++) {
            const int n = n_base + nt * 8 + g8;
            u32 bh0 = *(const u32*)&X0[n * PADK + k0];
            u32 bh1 = *(const u32*)&X0[n * PADK + k0 + 8];
            u32 bl0 = *(const u32*)&X1[n * PADK + k0];
            u32 bl1 = *(const u32*)&X1[n * PADK + k0 + 8];
#pragma unroll
            for (int mt = 0; mt < 2; mt++) {
                mma16816(D[mt][nt], ah[mt], bh0, bh1);
                mma16816(D[mt][nt], ah[mt], bl0, bl1);
                mma16816(D[mt][nt], al[mt], bh0, bh1);
            }
        }
    }
#pragma unroll
    for (int mt = 0; mt < 2; mt++) {
        const int mrow = w0 * 16 + mt * 64 + g8;
#pragma unroll
        for (int nt = 0; nt < 4; nt++) {
            const int n = n_base + nt * 8 + 2 * tg;
            s.Gf[n][mrow]         = D[mt][nt][0];
            s.Gf[n + 1][mrow]     = D[mt][nt][1];
            s.Gf[n][mrow + 8]     = D[mt][nt][2];
            s.Gf[n + 1][mrow + 8] = D[mt][nt][3];
        }
    }
}

// epilogue: gates(+bias) -> c,h -> bf16 hi/lo tiles; thread owns (b, d0..d0+7)
__device__ __forceinline__ void epilogue(SM& s, int l, int b, int d0, float* C) {
    float gi[8], gf_[8], gg[8], go[8];
    *(float4*)&gi[0]  = *(const float4*)&s.Gf[b][d0];
    *(float4*)&gi[4]  = *(const float4*)&s.Gf[b][d0 + 4];
    *(float4*)&gf_[0] = *(const float4*)&s.Gf[b][32 + d0];
    *(float4*)&gf_[4] = *(const float4*)&s.Gf[b][32 + d0 + 4];
    *(float4*)&gg[0]  = *(const float4*)&s.Gf[b][64 + d0];
    *(float4*)&gg[4]  = *(const float4*)&s.Gf[b][64 + d0 + 4];
    *(float4*)&go[0]  = *(const float4*)&s.Gf[b][96 + d0];
    *(float4*)&go[4]  = *(const float4*)&s.Gf[b][96 + d0 + 4];
    const float* bb = &s.bsum[l][0];
    float bi[8], bf2[8], bg[8], bo[8];
    *(float4*)&bi[0]  = *(const float4*)(bb + d0);      *(float4*)&bi[4]  = *(const float4*)(bb + d0 + 4);
    *(float4*)&bf2[0] = *(const float4*)(bb + 32 + d0); *(float4*)&bf2[4] = *(const float4*)(bb + 32 + d0 + 4);
    *(float4*)&bg[0]  = *(const float4*)(bb + 64 + d0); *(float4*)&bg[4]  = *(const float4*)(bb + 64 + d0 + 4);
    *(float4*)&bo[0]  = *(const float4*)(bb + 96 + d0); *(float4*)&bo[4]  = *(const float4*)(bb + 96 + d0 + 4);
    float ch[8], cl[8], hh[8], hl[8];
#pragma unroll
    for (int j = 0; j < 8; j++) {
        float c = fmaf(sigm(gf_[j] + bf2[j]), C[j], sigm(gi[j] + bi[j]) * tanha(gg[j] + bg[j]));
        float h = sigm(go[j] + bo[j]) * tanha(c);
        C[j] = c;
        float chi = __bfloat162float(__float2bfloat16(c));
        float hhi = __bfloat162float(__float2bfloat16(h));
        ch[j] = chi; cl[j] = c - chi;
        hh[j] = hhi; hl[j] = h - hhi;
        if (l == 2) s.c2f[d0 + j][b] = c;
    }
    uint4 q;
    q.x = pkbf(hh[0], hh[1]); q.y = pkbf(hh[2], hh[3]);
    q.z = pkbf(hh[4], hh[5]); q.w = pkbf(hh[6], hh[7]);
    *(uint4*)&s.Xt[l][0][b * PADK + 32 + d0] = q;
    q.x = pkbf(hl[0], hl[1]); q.y = pkbf(hl[2], hl[3]);
    q.z = pkbf(hl[4], hl[5]); q.w = pkbf(hl[6], hl[7]);
    *(uint4*)&s.Xt[l][1][b * PADK + 32 + d0] = q;
    if (l < 2) {
        q.x = pkbf(ch[0], ch[1]); q.y = pkbf(ch[2], ch[3]);
        q.z = pkbf(ch[4], ch[5]); q.w = pkbf(ch[6], ch[7]);
        *(uint4*)&s.Xt[l + 1][0][b * PADK + d0] = q;
        q.x = pkbf(cl[0], cl[1]); q.y = pkbf(cl[2], cl[3]);
        q.z = pkbf(cl[4], cl[5]); q.w = pkbf(cl[6], cl[7]);
        *(uint4*)&s.Xt[l + 1][1][b * PADK + d0] = q;
    }
}

__global__ void __launch_bounds__(NTHR, 1)
kalman_lstm_kernel(const float* __restrict__ hist,
                   const float* __restrict__ mx,  const float* __restrict__ my,
                   const float* __restrict__ vsx, const float* __restrict__ asx,
                   const float* __restrict__ Rxp, const float* __restrict__ Ryp,
                   const float* __restrict__ Gx,  const float* __restrict__ Gy,
                   const float* __restrict__ WinW, const float* __restrict__ Winb,
                   const float* __restrict__ eWih, const float* __restrict__ eWhh,
                   const float* __restrict__ ebih, const float* __restrict__ ebhh,
                   const float* __restrict__ dWih, const float* __restrict__ dWhh,
                   const float* __restrict__ dbih, const float* __restrict__ dbhh,
                   const float* __restrict__ WoutW, const float* __restrict__ Woutb,
                   float* __restrict__ out)
{
    extern __shared__ char smraw[];
    SM& s = *reinterpret_cast<SM*>(smraw);
    const int tid  = threadIdx.x;
    const int wid  = tid >> 5, lane = tid & 31;
    const int b0   = blockIdx.x * BT;
    const int grp  = wid >> 2;           // 0: batch 0-31, 1: batch 32-63
    const int w0   = wid & 3;            // local warp
    const int ltid = tid & 127;          // local tid in group
    const int b    = grp * 32 + (ltid & 31);   // batch column for epilogue/input
    const int d0   = (ltid >> 5) * 8;          // d octet for epilogue/input

    // ---- one-time setup (full CTA) ----
    pack_wts(s, tid, eWih, eWhh, ebih, ebhh);
    for (int i = tid; i < 24 * 32; i += NTHR) {
        int d = i & 31, k = i >> 5;
        s.WinT[k][d] = WinW[d * 24 + k];
    }
    if (tid < 32) s.Winb[tid] = Winb[tid];
    if (tid < 128) { int k = tid >> 2, qq = tid & 3; s.WoutT[k][qq] = WoutW[qq * 32 + k]; }
    if (tid < 4)  s.Woutb[tid] = Woutb[tid];
    for (int i = tid; i < BT * 40; i += NTHR) {
        int bb2 = i / 40, j = i % 40;
        s.Zs[j & 1][j >> 1][bb2] = hist[(size_t)(b0 + bb2) * 40 + j];
    }
    for (int i = tid; i < (int)(sizeof(s.Xt) / 4); i += NTHR)
        ((u32*)&s.Xt[0][0][0])[i] = 0u;

    const float rx = Rxp[0] * Rxp[0], ry = Ryp[0] * Ryp[0];
    const float vv = vsx[0] * vsx[0], aa = asx[0] * asx[0];
    const float gxe0 = Gx[0] * mx[0], gxe1 = Gx[1] * mx[0], gxe2 = Gx[2] * mx[0];
    const float gye0 = Gy[0] * my[0], gye1 = Gy[1] * my[0], gye2 = Gy[2] * my[0];
    const float gx0 = Gx[0], gx1 = Gx[1], gx2 = Gx[2];
    const float gy0 = Gy[0], gy1 = Gy[1], gy2 = Gy[2];

    if (tid < BT) {
#pragma unroll
        for (int j = 0; j < 24; j++) s.XP[j][tid] = 0.f;
        s.XP[0][tid]  = hist[(size_t)(b0 + tid) * 40 + 0];
        s.XP[3][tid]  = hist[(size_t)(b0 + tid) * 40 + 1];
        s.XP[6][tid]  = rx; s.XP[10][tid] = vv; s.XP[14][tid] = aa;
        s.XP[15][tid] = rx; s.XP[19][tid] = vv; s.XP[23][tid] = aa;
    }

    float Creg[3][8];
#pragma unroll
    for (int l = 0; l < 3; l++)
#pragma unroll
        for (int j = 0; j < 8; j++) Creg[l][j] = 0.f;

    __syncthreads();

    // ================= encoder: t = 1..19 (per-group pipeline) =================
    for (int t = 1; t < TH; t++) {
        input_layer(s, b, d0);
        barg(grp);
#pragma unroll 1
        for (int l = 0; l < 3; l++) {
            do_layer_mma(s, l, w0, lane, grp);
            barg(grp);
            epilogue(s, l, b, d0, Creg[l]);
            barg(grp);
        }
        if (ltid < 64) {
            int bb2 = grp * 32 + (ltid & 31), f = ltid >> 5;
            int xo = f ? 3 : 0, po = f ? 15 : 6;
            float X[3], P[9];
#pragma unroll
            for (int i = 0; i < 3; i++) X[i] = s.XP[xo + i][bb2];
#pragma unroll
            for (int i = 0; i < 9; i++) P[i] = s.XP[po + i][bb2];
            if (f == 0) kpred_f(X, P, gxe0, gxe1, gxe2);
            else        kpred_f(X, P, gye0, gye1, gye2);
            kupd_f(X, P, s.Zs[f][t][bb2], f ? ry : rx);
#pragma unroll
            for (int i = 0; i < 3; i++) s.XP[xo + i][bb2] = X[i];
#pragma unroll
            for (int i = 0; i < 9; i++) s.XP[po + i][bb2] = P[i];
        }
        barg(grp);
    }

    // ---- swap in decoder weights (full CTA) ----
    __syncthreads();
    pack_wts(s, tid, dWih, dWhh, dbih, dbhh);
    __syncthreads();

    // ================= decoder: 30 steps (per-group pipeline) =================
    for (int st = 0; st < LP; st++) {
        input_layer(s, b, d0);
        barg(grp);
#pragma unroll 1
        for (int l = 0; l < 3; l++) {
            do_layer_mma(s, l, w0, lane, grp);
            barg(grp);
            epilogue(s, l, b, d0, Creg[l]);
            barg(grp);
        }
        // pred = c2 @ Wout^T + b : 128 threads = 4q x 32b
        {
            int qq = ltid >> 5, bb2 = grp * 32 + (ltid & 31);
            float a = s.Woutb[qq];
#pragma unroll 8
            for (int k = 0; k < 32; k++) a = fmaf(s.c2f[k][bb2], s.WoutT[k][qq], a);
            s.pred[qq][bb2] = a;
        }
        barg(grp);
        if (ltid < 64) {
            int bb2 = grp * 32 + (ltid & 31), f = ltid >> 5;
            int xo = f ? 3 : 0, po = f ? 15 : 6;
            float X[3], P[9];
#pragma unroll
            for (int i = 0; i < 3; i++) X[i] = s.XP[xo + i][bb2];
#pragma unroll
            for (int i = 0; i < 9; i++) P[i] = s.XP[po + i][bb2];
            X[2] = DTC * s.pred[f][bb2];
            float sc = s.pred[2 + f][bb2];
            float q0 = sc * (f ? gy0 : gx0);
            float q1 = sc * (f ? gy1 : gx1);
            float q2 = sc * (f ? gy2 : gx2);
            kpred_f(X, P, q0, q1, q2);
#pragma unroll
            for (int i = 0; i < 3; i++) s.XP[xo + i][bb2] = X[i];
#pragma unroll
            for (int i = 0; i < 9; i++) s.XP[po + i][bb2] = P[i];
            float* o = out + (size_t)(b0 + bb2) * (LP * 5) + st * 5;
            if (f == 0) { o[0] = X[0]; o[2] = sqrtf(P[0]); }
            else        { o[1] = X[0]; o[3] = sqrtf(P[0]); o[4] = 0.0f; }
        }
        barg(grp);
    }
}

extern "C" void kernel_launch(void* const* d_in, const int* in_sizes, int n_in,
                              void* d_out, int out_size) {
    cudaFuncSetAttribute(kalman_lstm_kernel,
                         cudaFuncAttributeMaxDynamicSharedMemorySize,
                         (int)sizeof(SM));
    kalman_lstm_kernel<<<NCTA, NTHR, sizeof(SM)>>>(
        (const float*)d_in[0],  (const float*)d_in[1],  (const float*)d_in[2],
        (const float*)d_in[3],  (const float*)d_in[4],  (const float*)d_in[5],
        (const float*)d_in[6],  (const float*)d_in[7],  (const float*)d_in[8],
        (const float*)d_in[9],  (const float*)d_in[10], (const float*)d_in[11],
        (const float*)d_in[12], (const float*)d_in[13], (const float*)d_in[14],
        (const float*)d_in[15], (const float*)d_in[16], (const float*)d_in[17],
        (const float*)d_in[18], (const float*)d_in[19], (const float*)d_in[20],
        (float*)d_out);
}

// round 15
// speedup vs baseline: 2.2533x; 1.2243x over previous
#include <cuda_runtime.h>
#include <cuda_bf16.h>
#include <math.h>

typedef unsigned int u32;

#define BT   64
#define NCTA 128
#define NTHR 256
#define TH   20
#define LP   30
#define DTC  0.1f
#define D2C  0.005f
#define PADK 72     // bf16 per row in W/X tiles (conflict-free frag loads)
#define CPAD 33     // c2f row pad

struct __align__(16) SM {
    __nv_bfloat16 Wt[3][2][128 * PADK];  // [layer][hi/lo][m][k] k=[x32|h32]
    __nv_bfloat16 Xt[3][2][64 * PADK];   // [layer][hi/lo][n][k] x cols 0-31, h cols 32-63
    float c2f[64][CPAD];                 // layer-2 c, [n][d]
    float XP[24][64];
    float Zs[2][TH][64];
    float bsum[3][128];
    float WinT[24][32];
    float Winb[32];
    float WoutT[32][4];
    float Woutb[4];
};

__device__ __forceinline__ void barg(int g) {
    asm volatile("bar.sync %0, %1;" :: "r"(g + 1), "r"(128) : "memory");
}
__device__ __forceinline__ float tanha(float x) {
    float y; asm("tanh.approx.f32 %0, %1;" : "=f"(y) : "f"(x)); return y;
}
__device__ __forceinline__ float sigm(float z) { return fmaf(tanha(0.5f * z), 0.5f, 0.5f); }
__device__ __forceinline__ u32 pkbf(float lo, float hi) {
    u32 r; asm("cvt.rn.bf16x2.f32 %0, %1, %2;" : "=r"(r) : "f"(hi), "f"(lo)); return r;
}
__device__ __forceinline__ void mma16816(float* d, const u32* a, u32 b0, u32 b1) {
    asm volatile("mma.sync.aligned.m16n8k16.row.col.f32.bf16.bf16.f32 "
        "{%0,%1,%2,%3}, {%4,%5,%6,%7}, {%8,%9}, {%0,%1,%2,%3};"
        : "+f"(d[0]), "+f"(d[1]), "+f"(d[2]), "+f"(d[3])
        : "r"(a[0]), "r"(a[1]), "r"(a[2]), "r"(a[3]), "r"(b0), "r"(b1));
}

__device__ __forceinline__ void pack_wts(SM& s, int tid,
        const float* __restrict__ Wih, const float* __restrict__ Whh,
        const float* __restrict__ bih, const float* __restrict__ bhh) {
    for (int i = tid; i < 3 * 128 * 64; i += NTHR) {
        int l = i >> 13, r = i & 8191, m = r >> 6, k = r & 63;
        float v = (k < 32) ? Wih[l * 4096 + m * 32 + k] : Whh[l * 4096 + m * 32 + (k - 32)];
        __nv_bfloat16 h = __float2bfloat16(v);
        s.Wt[l][0][m * PADK + k] = h;
        s.Wt[l][1][m * PADK + k] = __float2bfloat16(v - __bfloat162float(h));
    }
    for (int i = tid; i < 384; i += NTHR)
        ((float*)s.bsum)[i] = bih[i] + bhh[i];
}

__device__ __forceinline__ void kpred_f(float X[3], float P[9], float g0, float g1, float g2) {
    X[0] = X[0] + DTC * X[1] + D2C * X[2];
    X[1] = X[1] + DTC * X[2];
    float A[9];
#pragma unroll
    for (int j = 0; j < 3; j++) {
        A[0 * 3 + j] = P[0 * 3 + j] + DTC * P[1 * 3 + j] + D2C * P[2 * 3 + j];
        A[1 * 3 + j] = P[1 * 3 + j] + DTC * P[2 * 3 + j];
        A[2 * 3 + j] = P[2 * 3 + j];
    }
#pragma unroll
    for (int i = 0; i < 3; i++) {
        float qi = (i == 0) ? g0 : ((i == 1) ? g1 : g2);
        P[i * 3 + 0] = A[i * 3 + 0] + DTC * A[i * 3 + 1] + D2C * A[i * 3 + 2] + qi * g0;
        P[i * 3 + 1] = A[i * 3 + 1] + DTC * A[i * 3 + 2] + qi * g1;
        P[i * 3 + 2] = A[i * 3 + 2] + qi * g2;
    }
}
__device__ __forceinline__ void kupd_f(float X[3], float P[9], float z, float R) {
    float y = z - X[0];
    float S = P[0] + R;
    float inv = 1.0f / S;
    float K0 = P[0] * inv, K1 = P[3] * inv, K2 = P[6] * inv;
    X[0] += y * K0; X[1] += y * K1; X[2] += y * K2;
    float r0 = P[0], r1 = P[1], r2 = P[2];
    P[0] -= K0 * r0; P[1] -= K0 * r1; P[2] -= K0 * r2;
    P[3] -= K1 * r0; P[4] -= K1 * r1; P[5] -= K1 * r2;
    P[6] -= K2 * r0; P[7] -= K2 * r1; P[8] -= K2 * r2;
}

// input layer: x[b][d0..d0+7] = tanh(XP[.][b] @ Win^T + b) -> Xt[0] hi/lo x-cols
__device__ __forceinline__ void input_layer(SM& s, int b, int d0) {
    float acc[8];
    *(float4*)&acc[0] = *(const float4*)&s.Winb[d0];
    *(float4*)&acc[4] = *(const float4*)&s.Winb[d0 + 4];
#pragma unroll
    for (int k = 0; k < 24; k++) {
        float xv = s.XP[k][b];
        float4 w0 = *(const float4*)&s.WinT[k][d0];
        float4 w1 = *(const float4*)&s.WinT[k][d0 + 4];
        acc[0] = fmaf(w0.x, xv, acc[0]); acc[1] = fmaf(w0.y, xv, acc[1]);
        acc[2] = fmaf(w0.z, xv, acc[2]); acc[3] = fmaf(w0.w, xv, acc[3]);
        acc[4] = fmaf(w1.x, xv, acc[4]); acc[5] = fmaf(w1.y, xv, acc[5]);
        acc[6] = fmaf(w1.z, xv, acc[6]); acc[7] = fmaf(w1.w, xv, acc[7]);
    }
    float xh[8], xl[8];
#pragma unroll
    for (int j = 0; j < 8; j++) {
        float x = tanha(acc[j]);
        float h = __bfloat162float(__float2bfloat16(x));
        xh[j] = h; xl[j] = x - h;
    }
    uint4 qh, ql;
    qh.x = pkbf(xh[0], xh[1]); qh.y = pkbf(xh[2], xh[3]);
    qh.z = pkbf(xh[4], xh[5]); qh.w = pkbf(xh[6], xh[7]);
    ql.x = pkbf(xl[0], xl[1]); ql.y = pkbf(xl[2], xl[3]);
    ql.z = pkbf(xl[4], xl[5]); ql.w = pkbf(xl[6], xl[7]);
    *(uint4*)&s.Xt[0][0][b * PADK + d0] = qh;
    *(uint4*)&s.Xt[0][1][b * PADK + d0] = ql;
}

// half-K GEMM into D[gi][nt][4]: kh=0 -> x cols (k 0-31), kh=1 -> h cols (k 32-63).
// Warp covers all 4 gate tiles for its d-slice (w0&1) and n-half (w0>>1).
__device__ __forceinline__ void mma_part(SM& s, int l, int kh, int w0, int lane, int grp,
                                         float (&D)[4][2][4], bool zero)
{
    const int g8 = lane >> 2, tg = lane & 3;
    const int d0 = (w0 & 1) * 16;
    const int nb = grp * 32 + (w0 >> 1) * 16;
    if (zero) {
#pragma unroll
        for (int gi = 0; gi < 4; gi++)
#pragma unroll
            for (int nt = 0; nt < 2; nt++)
#pragma unroll
                for (int j = 0; j < 4; j++) D[gi][nt][j] = 0.f;
    }
    const __nv_bfloat16* __restrict__ W0 = &s.Wt[l][0][0];
    const __nv_bfloat16* __restrict__ W1 = &s.Wt[l][1][0];
    const __nv_bfloat16* __restrict__ X0 = &s.Xt[l][0][0];
    const __nv_bfloat16* __restrict__ X1 = &s.Xt[l][1][0];
#pragma unroll
    for (int kk = 0; kk < 2; kk++) {
        const int k0 = (kh * 2 + kk) * 16 + 2 * tg;
        u32 ah[4][4], al[4][4];
#pragma unroll
        for (int gi = 0; gi < 4; gi++) {
            const int m = gi * 32 + d0 + g8;
            ah[gi][0] = *(const u32*)&W0[m * PADK + k0];
            ah[gi][1] = *(const u32*)&W0[(m + 8) * PADK + k0];
            ah[gi][2] = *(const u32*)&W0[m * PADK + k0 + 8];
            ah[gi][3] = *(const u32*)&W0[(m + 8) * PADK + k0 + 8];
            al[gi][0] = *(const u32*)&W1[m * PADK + k0];
            al[gi][1] = *(const u32*)&W1[(m + 8) * PADK + k0];
            al[gi][2] = *(const u32*)&W1[m * PADK + k0 + 8];
            al[gi][3] = *(const u32*)&W1[(m + 8) * PADK + k0 + 8];
        }
#pragma unroll
        for (int nt = 0; nt < 2; nt++) {
            const int n = nb + nt * 8 + g8;
            u32 bh0 = *(const u32*)&X0[n * PADK + k0];
            u32 bh1 = *(const u32*)&X0[n * PADK + k0 + 8];
            u32 bl0 = *(const u32*)&X1[n * PADK + k0];
            u32 bl1 = *(const u32*)&X1[n * PADK + k0 + 8];
#pragma unroll
            for (int gi = 0; gi < 4; gi++) {
                mma16816(D[gi][nt], ah[gi], bh0, bh1);
                mma16816(D[gi][nt], ah[gi], bl0, bl1);
                mma16816(D[gi][nt], al[gi], bh0, bh1);
            }
        }
    }
}

// in-register epilogue: gates in D -> c,h -> bf16 hi/lo tiles (+ c2f for l==2)
__device__ __forceinline__ void epilogue(SM& s, int l, int w0, int lane, int grp,
                                         float (&D)[4][2][4], float* C)
{
    const int g8 = lane >> 2, tg = lane & 3;
    const int d0 = (w0 & 1) * 16;
    const int nb = grp * 32 + (w0 >> 1) * 16;
    const float* bb = &s.bsum[l][0];
    __nv_bfloat16* __restrict__ H0 = &s.Xt[l][0][0];
    __nv_bfloat16* __restrict__ H1 = &s.Xt[l][1][0];
#pragma unroll
    for (int dd = 0; dd < 2; dd++) {
        const int d = d0 + g8 + dd * 8;
        const float bi = bb[d], bf_ = bb[32 + d], bg = bb[64 + d], bo = bb[96 + d];
#pragma unroll
        for (int nt = 0; nt < 2; nt++) {
#pragma unroll
            for (int dn = 0; dn < 2; dn++) {
                const int j = dn + dd * 2;
                const int n = nb + nt * 8 + 2 * tg + dn;
                const int ci = dd * 4 + nt * 2 + dn;
                float c = fmaf(sigm(D[1][nt][j] + bf_), C[ci],
                               sigm(D[0][nt][j] + bi) * tanha(D[2][nt][j] + bg));
                float h = sigm(D[3][nt][j] + bo) * tanha(c);
                C[ci] = c;
                __nv_bfloat16 hh = __float2bfloat16(h);
                H0[n * PADK + 32 + d] = hh;
                H1[n * PADK + 32 + d] = __float2bfloat16(h - __bfloat162float(hh));
                if (l < 2) {
                    __nv_bfloat16 ch = __float2bfloat16(c);
                    s.Xt[l + 1][0][n * PADK + d] = ch;
                    s.Xt[l + 1][1][n * PADK + d] = __float2bfloat16(c - __bfloat162float(ch));
                } else {
                    s.c2f[n][d] = c;
                }
            }
        }
    }
}

__global__ void __launch_bounds__(NTHR, 1)
kalman_lstm_kernel(const float* __restrict__ hist,
                   const float* __restrict__ mx,  const float* __restrict__ my,
                   const float* __restrict__ vsx, const float* __restrict__ asx,
                   const float* __restrict__ Rxp, const float* __restrict__ Ryp,
                   const float* __restrict__ Gx,  const float* __restrict__ Gy,
                   const float* __restrict__ WinW, const float* __restrict__ Winb,
                   const float* __restrict__ eWih, const float* __restrict__ eWhh,
                   const float* __restrict__ ebih, const float* __restrict__ ebhh,
                   const float* __restrict__ dWih, const float* __restrict__ dWhh,
                   const float* __restrict__ dbih, const float* __restrict__ dbhh,
                   const float* __restrict__ WoutW, const float* __restrict__ Woutb,
                   float* __restrict__ out)
{
    extern __shared__ char smraw[];
    SM& s = *reinterpret_cast<SM*>(smraw);
    const int tid  = threadIdx.x;
    const int wid  = tid >> 5, lane = tid & 31;
    const int b0   = blockIdx.x * BT;
    const int grp  = wid >> 2;
    const int w0   = wid & 3;
    const int ltid = tid & 127;
    const int b    = grp * 32 + (ltid & 31);
    const int d0o  = (ltid >> 5) * 8;

    // ---- one-time setup (full CTA) ----
    pack_wts(s, tid, eWih, eWhh, ebih, ebhh);
    for (int i = tid; i < 24 * 32; i += NTHR) {
        int d = i & 31, k = i >> 5;
        s.WinT[k][d] = WinW[d * 24 + k];
    }
    if (tid < 32) s.Winb[tid] = Winb[tid];
    if (tid < 128) { int k = tid >> 2, qq = tid & 3; s.WoutT[k][qq] = WoutW[qq * 32 + k]; }
    if (tid < 4)  s.Woutb[tid] = Woutb[tid];
    for (int i = tid; i < BT * 40; i += NTHR) {
        int bb2 = i / 40, j = i % 40;
        s.Zs[j & 1][j >> 1][bb2] = hist[(size_t)(b0 + bb2) * 40 + j];
    }
    for (int i = tid; i < (int)(sizeof(s.Xt) / 4); i += NTHR)
        ((u32*)&s.Xt[0][0][0])[i] = 0u;

    const float rx = Rxp[0] * Rxp[0], ry = Ryp[0] * Ryp[0];
    const float vv = vsx[0] * vsx[0], aa = asx[0] * asx[0];
    const float gxe0 = Gx[0] * mx[0], gxe1 = Gx[1] * mx[0], gxe2 = Gx[2] * mx[0];
    const float gye0 = Gy[0] * my[0], gye1 = Gy[1] * my[0], gye2 = Gy[2] * my[0];
    const float gx0 = Gx[0], gx1 = Gx[1], gx2 = Gx[2];
    const float gy0 = Gy[0], gy1 = Gy[1], gy2 = Gy[2];

    if (tid < BT) {
#pragma unroll
        for (int j = 0; j < 24; j++) s.XP[j][tid] = 0.f;
        s.XP[0][tid]  = hist[(size_t)(b0 + tid) * 40 + 0];
        s.XP[3][tid]  = hist[(size_t)(b0 + tid) * 40 + 1];
        s.XP[6][tid]  = rx; s.XP[10][tid] = vv; s.XP[14][tid] = aa;
        s.XP[15][tid] = rx; s.XP[19][tid] = vv; s.XP[23][tid] = aa;
    }

    float Creg[3][8];
#pragma unroll
    for (int l = 0; l < 3; l++)
#pragma unroll
        for (int j = 0; j < 8; j++) Creg[l][j] = 0.f;

    float D[3][4][2][4];   // one accumulator set per layer (static indexing)
    __syncthreads();

    // initial h-part prefetch for layer 0 (h = 0 tiles, but keeps structure uniform)
    mma_part(s, 0, 1, w0, lane, grp, D[0], true);

    // ================= encoder: t = 1..19 =================
    for (int t = 1; t < TH; t++) {
        input_layer(s, b, d0o);
        barg(grp);
        // S1
        mma_part(s, 0, 0, w0, lane, grp, D[0], false);
        mma_part(s, 1, 1, w0, lane, grp, D[1], true);
        epilogue(s, 0, w0, lane, grp, D[0], Creg[0]);
        barg(grp);
        // S2
        mma_part(s, 1, 0, w0, lane, grp, D[1], false);
        mma_part(s, 2, 1, w0, lane, grp, D[2], true);
        epilogue(s, 1, w0, lane, grp, D[1], Creg[1]);
        barg(grp);
        // S3
        mma_part(s, 2, 0, w0, lane, grp, D[2], false);
        if (t < TH - 1)
            mma_part(s, 0, 1, w0, lane, grp, D[0], true);   // next step's h(0)
        epilogue(s, 2, w0, lane, grp, D[2], Creg[2]);
        if (ltid < 64) {
            int bb2 = grp * 32 + (ltid & 31), f = ltid >> 5;
            int xo = f ? 3 : 0, po = f ? 15 : 6;
            float X[3], P[9];
#pragma unroll
            for (int i = 0; i < 3; i++) X[i] = s.XP[xo + i][bb2];
#pragma unroll
            for (int i = 0; i < 9; i++) P[i] = s.XP[po + i][bb2];
            if (f == 0) kpred_f(X, P, gxe0, gxe1, gxe2);
            else        kpred_f(X, P, gye0, gye1, gye2);
            kupd_f(X, P, s.Zs[f][t][bb2], f ? ry : rx);
#pragma unroll
            for (int i = 0; i < 3; i++) s.XP[xo + i][bb2] = X[i];
#pragma unroll
            for (int i = 0; i < 9; i++) s.XP[po + i][bb2] = P[i];
        }
        barg(grp);
    }

    // ---- swap in decoder weights (full CTA) ----
    __syncthreads();
    pack_wts(s, tid, dWih, dWhh, dbih, dbhh);
    __syncthreads();
    mma_part(s, 0, 1, w0, lane, grp, D[0], true);   // h(0) with decoder weights

    // ================= decoder: 30 steps =================
    for (int st = 0; st < LP; st++) {
        input_layer(s, b, d0o);
        barg(grp);
        mma_part(s, 0, 0, w0, lane, grp, D[0], false);
        mma_part(s, 1, 1, w0, lane, grp, D[1], true);
        epilogue(s, 0, w0, lane, grp, D[0], Creg[0]);
        barg(grp);
        mma_part(s, 1, 0, w0, lane, grp, D[1], false);
        mma_part(s, 2, 1, w0, lane, grp, D[2], true);
        epilogue(s, 1, w0, lane, grp, D[1], Creg[1]);
        barg(grp);
        mma_part(s, 2, 0, w0, lane, grp, D[2], false);
        if (st < LP - 1)
            mma_part(s, 0, 1, w0, lane, grp, D[0], true);
        epilogue(s, 2, w0, lane, grp, D[2], Creg[2]);
        barg(grp);
        // pred (inline) + Kalman
        if (ltid < 64) {
            int bb2 = grp * 32 + (ltid & 31), f = ltid >> 5;
            float a0 = s.Woutb[f], a1 = s.Woutb[2 + f];
#pragma unroll 8
            for (int k = 0; k < 32; k++) {
                float cv = s.c2f[bb2][k];
                a0 = fmaf(cv, s.WoutT[k][f], a0);
                a1 = fmaf(cv, s.WoutT[k][2 + f], a1);
            }
            int xo = f ? 3 : 0, po = f ? 15 : 6;
            float X[3], P[9];
#pragma unroll
            for (int i = 0; i < 3; i++) X[i] = s.XP[xo + i][bb2];
#pragma unroll
            for (int i = 0; i < 9; i++) P[i] = s.XP[po + i][bb2];
            X[2] = DTC * a0;
            float q0 = a1 * (f ? gy0 : gx0);
            float q1 = a1 * (f ? gy1 : gx1);
            float q2 = a1 * (f ? gy2 : gx2);
            kpred_f(X, P, q0, q1, q2);
#pragma unroll
            for (int i = 0; i < 3; i++) s.XP[xo + i][bb2] = X[i];
#pragma unroll
            for (int i = 0; i < 9; i++) s.XP[po + i][bb2] = P[i];
            float* o = out + (size_t)(b0 + bb2) * (LP * 5) + st * 5;
            if (f == 0) { o[0] = X[0]; o[2] = sqrtf(P[0]); }
            else        { o[1] = X[0]; o[3] = sqrtf(P[0]); o[4] = 0.0f; }
        }
        barg(grp);
    }
}

extern "C" void kernel_launch(void* const* d_in, const int* in_sizes, int n_in,
                              void* d_out, int out_size) {
    cudaFuncSetAttribute(kalman_lstm_kernel,
                         cudaFuncAttributeMaxDynamicSharedMemorySize,
                         (int)sizeof(SM));
    kalman_lstm_kernel<<<NCTA, NTHR, sizeof(SM)>>>(
        (const float*)d_in[0],  (const float*)d_in[1],  (const float*)d_in[2],
        (const float*)d_in[3],  (const float*)d_in[4],  (const float*)d_in[5],
        (const float*)d_in[6],  (const float*)d_in[7],  (const float*)d_in[8],
        (const float*)d_in[9],  (const float*)d_in[10], (const float*)d_in[11],
        (const float*)d_in[12], (const float*)d_in[13], (const float*)d_in[14],
        (const float*)d_in[15], (const float*)d_in[16], (const float*)d_in[17],
        (const float*)d_in[18], (const float*)d_in[19], (const float*)d_in[20],
        (float*)d_out);
}